// round 13
// baseline (speedup 1.0000x reference)
#include <cuda_runtime.h>
#include <cuda_fp16.h>
#include <math.h>
#include <stdint.h>

// Problem constants
#define BB 2
#define SS 2048
#define EE 512
#define HH 8
#define DD 64
#define MM (BB * SS)   // 4096 rows

// Scratch (device globals; no allocation allowed)
__device__ float g_proj[MM * EE];

// fp16 operand arrays
__device__ __align__(16) __half g_Ax_hi[MM * EE];       // x split (qkv gemm A)
__device__ __align__(16) __half g_Ax_lo[MM * EE];
__device__ __align__(16) __half g_Qh[16 * 2048 * 64];   // [bh][s][d]
__device__ __align__(16) __half g_Ql[16 * 2048 * 64];
__device__ __align__(16) __half g_Kh[16 * 2048 * 64];
__device__ __align__(16) __half g_Kl[16 * 2048 * 64];
__device__ __align__(16) __half g_Vh[16 * 2048 * 64];   // single fp16
__device__ __align__(16) __half g_Av[MM * EE];          // attention out, single fp16
__device__ __align__(16) __half g_Bqkv_hi[3 * EE * EE]; // [n=z*512+h*64+d][e]
__device__ __align__(16) __half g_Bqkv_lo[3 * EE * EE];
__device__ __align__(16) __half g_Bp_hi[EE * EE];       // [n][k] = Wp[n][k]
__device__ __align__(16) __half g_Bp_lo[EE * EE];

// ---------------------------------------------------------------------------
// helpers
// ---------------------------------------------------------------------------
__device__ __forceinline__ uint32_t smem_u32(const void* p) {
    uint32_t a;
    asm("{ .reg .u64 t; cvta.to.shared.u64 t, %1; cvt.u32.u64 %0, t; }"
        : "=r"(a) : "l"(p));
    return a;
}
__device__ __forceinline__ uint32_t sw128(uint32_t off) {
    return off ^ ((off >> 3) & 0x70);
}
__device__ __forceinline__ void cpasync16(uint32_t dst, const void* src) {
    asm volatile("cp.async.cg.shared.global [%0], [%1], 16;"
                 :: "r"(dst), "l"(src) : "memory");
}
template <int N>
__device__ __forceinline__ void waitg() {
    asm volatile("cp.async.wait_group %0;" :: "n"(N) : "memory");
}
__device__ __forceinline__ void commitg() {
    asm volatile("cp.async.commit_group;" ::: "memory");
}
__device__ __forceinline__ void ldsm4(uint32_t& r0, uint32_t& r1, uint32_t& r2,
                                      uint32_t& r3, uint32_t a) {
    asm volatile("ldmatrix.sync.aligned.m8n8.x4.shared.b16 {%0,%1,%2,%3}, [%4];"
                 : "=r"(r0), "=r"(r1), "=r"(r2), "=r"(r3) : "r"(a));
}
__device__ __forceinline__ void ldsm4t(uint32_t& r0, uint32_t& r1, uint32_t& r2,
                                       uint32_t& r3, uint32_t a) {
    asm volatile("ldmatrix.sync.aligned.m8n8.x4.trans.shared.b16 {%0,%1,%2,%3}, [%4];"
                 : "=r"(r0), "=r"(r1), "=r"(r2), "=r"(r3) : "r"(a));
}
__device__ __forceinline__ void mma16816(float* c, const uint32_t* a,
                                         uint32_t b0, uint32_t b1) {
    asm volatile(
        "mma.sync.aligned.m16n8k16.row.col.f32.f16.f16.f32 "
        "{%0,%1,%2,%3}, {%4,%5,%6,%7}, {%8,%9}, {%0,%1,%2,%3};"
        : "+f"(c[0]), "+f"(c[1]), "+f"(c[2]), "+f"(c[3])
        : "r"(a[0]), "r"(a[1]), "r"(a[2]), "r"(a[3]), "r"(b0), "r"(b1));
}
__device__ __forceinline__ uint32_t packh2(float a, float b) {
    __half ha = __float2half_rn(a), hb = __float2half_rn(b);
    return (uint32_t)__half_as_ushort(ha) |
           ((uint32_t)__half_as_ushort(hb) << 16);
}
__device__ __forceinline__ void split2h(float a, float b, uint32_t& hi, uint32_t& lo) {
    __half ha = __float2half_rn(a), hb = __float2half_rn(b);
    float ra = a - __half2float(ha), rb = b - __half2float(hb);
    hi = (uint32_t)__half_as_ushort(ha) |
         ((uint32_t)__half_as_ushort(hb) << 16);
    __half la = __float2half_rn(ra), lb = __float2half_rn(rb);
    lo = (uint32_t)__half_as_ushort(la) |
         ((uint32_t)__half_as_ushort(lb) << 16);
}

// ---------------------------------------------------------------------------
// Merged, vectorized prep: wqkv hi/lo, wp hi/lo, x hi/lo — ONE launch.
// ---------------------------------------------------------------------------
#define N_WQKV (3 * EE * EE)            // 786432
#define N_WP   (EE * EE)                // 262144
#define N_X    (MM * EE)                // 2097152
#define PREP_BLOCKS ((N_WQKV + N_WP + N_X) / 4 / 256)   // 3072

__global__ void prep_all_kernel(const float* __restrict__ Wq,
                                const float* __restrict__ Wk,
                                const float* __restrict__ Wv,
                                const float* __restrict__ Wp,
                                const float* __restrict__ x) {
    int idx = (blockIdx.x * 256 + threadIdx.x) * 4;
    if (idx < N_WQKV) {
        int n = idx >> 9, e0 = idx & 511;
        int z = n >> 9, h = (n >> 6) & 7, d = n & 63;
        const float* W = (z == 0) ? Wq : ((z == 1) ? Wk : Wv);
        uint32_t h0, l0, h1, l1;
        float v0 = W[((size_t)h * EE + e0 + 0) * DD + d];
        float v1 = W[((size_t)h * EE + e0 + 1) * DD + d];
        float v2 = W[((size_t)h * EE + e0 + 2) * DD + d];
        float v3 = W[((size_t)h * EE + e0 + 3) * DD + d];
        split2h(v0, v1, h0, l0);
        split2h(v2, v3, h1, l1);
        *(uint2*)(g_Bqkv_hi + idx) = make_uint2(h0, h1);
        *(uint2*)(g_Bqkv_lo + idx) = make_uint2(l0, l1);
    } else if (idx < N_WQKV + N_WP) {
        int i = idx - N_WQKV;
        float4 v = *(const float4*)(Wp + i);
        uint32_t h0, l0, h1, l1;
        split2h(v.x, v.y, h0, l0);
        split2h(v.z, v.w, h1, l1);
        *(uint2*)(g_Bp_hi + i) = make_uint2(h0, h1);
        *(uint2*)(g_Bp_lo + i) = make_uint2(l0, l1);
    } else {
        int i = idx - N_WQKV - N_WP;
        float4 v = *(const float4*)(x + i);
        uint32_t h0, l0, h1, l1;
        split2h(v.x, v.y, h0, l0);
        split2h(v.z, v.w, h1, l1);
        *(uint2*)(g_Ax_hi + i) = make_uint2(h0, h1);
        *(uint2*)(g_Ax_lo + i) = make_uint2(l0, l1);
    }
}

// ---------------------------------------------------------------------------
// QKV GEMM: C[128 x 128] tile of x[M x 512] * Wqkv[N x 512]^T. fp32 accum.
// Q/K tiles (y<8): 3-pass (AhBh+AhBl+AlBh) -> hi/lo fp16 out.
// V tiles (y>=8): 2-pass (AhBh+AlBh) -> single fp16 out.
// 256 threads = 8 warps (4m x 2n). 3-stage cp.async pipeline (k=64).
// ---------------------------------------------------------------------------
#define STAGE_BYTES 65536
#define GEMM_SMEM (3 * STAGE_BYTES)   // 196608

__global__ __launch_bounds__(256, 1)
void gemm_mma_kernel(const float* __restrict__ x) {
    extern __shared__ char sm[];
    const uint32_t smb = smem_u32(sm);
    const int t = threadIdx.x;
    const int w = t >> 5, l = t & 31;
    const int wm = w & 3, wn = w >> 2;
    const int gid = l >> 2, tig = l & 3;
    const int m0 = blockIdx.x * 128;
    const int n0 = blockIdx.y * 128;

    const bool useBl = (blockIdx.y < 8);     // pass Ah·Bl (Q/K only)

    float acc[2][8][4];
#pragma unroll
    for (int i = 0; i < 2; i++)
#pragma unroll
        for (int j = 0; j < 8; j++)
#pragma unroll
            for (int c = 0; c < 4; c++) acc[i][j][c] = 0.f;

    auto issue_stage = [&](int s) {
        const int k0 = s * 64;
        const uint32_t sb = smb + (s % 3) * STAGE_BYTES;
        const __half* gsrc[4] = {g_Ax_hi, g_Ax_lo, g_Bqkv_hi, g_Bqkv_lo};
#pragma unroll
        for (int tl = 0; tl < 4; tl++) {
            if (tl == 3 && !useBl) continue;
            const uint32_t tbase = sb + tl * 16384;
            const __half* g = gsrc[tl];
            const int rbase = (tl < 2) ? m0 : n0;
#pragma unroll
            for (int i = 0; i < 4; i++) {
                int c = t + 256 * i;
                int row = c >> 3, cb = c & 7;
                uint32_t dst = tbase + sw128((uint32_t)(row * 128 + cb * 16));
                const __half* src =
                    g + (size_t)(rbase + row) * EE + k0 + cb * 8;
                cpasync16(dst, src);
            }
        }
        commitg();
    };

    issue_stage(0);
    issue_stage(1);

    const int li = l >> 3;
    const int lr = l & 7;

    for (int s = 0; s < 8; s++) {
        if (s < 7) waitg<1>(); else waitg<0>();
        __syncthreads();
        if (s + 2 < 8) issue_stage(s + 2);

        const uint32_t sb = smb + (s % 3) * STAGE_BYTES;

#pragma unroll
        for (int kk = 0; kk < 4; kk++) {
            uint32_t ah[2][4], al[2][4];
#pragma unroll
            for (int mt = 0; mt < 2; mt++) {
                int row = wm * 32 + mt * 16 + (li & 1) * 8 + lr;
                int cb = kk * 2 + (li >> 1);
                uint32_t off = sw128((uint32_t)(row * 128 + cb * 16));
                ldsm4(ah[mt][0], ah[mt][1], ah[mt][2], ah[mt][3], sb + off);
                ldsm4(al[mt][0], al[mt][1], al[mt][2], al[mt][3],
                      sb + 16384 + off);
            }
#pragma unroll
            for (int h2 = 0; h2 < 2; h2++) {
                uint32_t bh[2][4], bl[2][4];
#pragma unroll
                for (int p2 = 0; p2 < 2; p2++) {
                    int ntb = h2 * 2 + p2;
                    int nrow = wn * 64 + ntb * 16 + (li >> 1) * 8 + lr;
                    int cb = kk * 2 + (li & 1);
                    uint32_t off = sw128((uint32_t)(nrow * 128 + cb * 16));
                    ldsm4(bh[p2][0], bh[p2][1], bh[p2][2], bh[p2][3],
                          sb + 32768 + off);
                    if (useBl)
                        ldsm4(bl[p2][0], bl[p2][1], bl[p2][2], bl[p2][3],
                              sb + 49152 + off);
                }
#pragma unroll
                for (int mt = 0; mt < 2; mt++)
#pragma unroll
                    for (int q = 0; q < 4; q++) {
                        int nt = h2 * 4 + q;
                        int p2 = q >> 1, od = q & 1;
                        float* c = acc[mt][nt];
                        mma16816(c, ah[mt], bh[p2][2 * od], bh[p2][2 * od + 1]);
                        if (useBl)
                            mma16816(c, ah[mt], bl[p2][2 * od], bl[p2][2 * od + 1]);
                        mma16816(c, al[mt], bh[p2][2 * od], bh[p2][2 * od + 1]);
                    }
            }
        }
    }

    // ---- epilogue ----
    const int row0 = m0 + wm * 32 + gid;
#pragma unroll
    for (int mt = 0; mt < 2; mt++) {
        int rg = row0 + mt * 16;
        int b = rg >> 11, sI = rg & 2047;
#pragma unroll
        for (int nt = 0; nt < 8; nt++) {
            int ng = n0 + wn * 64 + nt * 8 + 2 * tig;
            int z = ng >> 9, r9 = ng & 511;
            int h = r9 >> 6, d = r9 & 63;
            size_t base = (((size_t)(b * HH + h)) * SS + sI) * DD + d;
            if (z == 2) {
                *(uint32_t*)(g_Vh + base) =
                    packh2(acc[mt][nt][0], acc[mt][nt][1]);
                *(uint32_t*)(g_Vh + base + 8 * DD) =
                    packh2(acc[mt][nt][2], acc[mt][nt][3]);
            } else {
                __half* oh = (z == 0) ? g_Qh : g_Kh;
                __half* ol = (z == 0) ? g_Ql : g_Kl;
                uint32_t hi, lo;
                split2h(acc[mt][nt][0], acc[mt][nt][1], hi, lo);
                *(uint32_t*)(oh + base) = hi;
                *(uint32_t*)(ol + base) = lo;
                split2h(acc[mt][nt][2], acc[mt][nt][3], hi, lo);
                *(uint32_t*)(oh + base + 8 * DD) = hi;
                *(uint32_t*)(ol + base + 8 * DD) = lo;
            }
        }
    }
}

// ---------------------------------------------------------------------------
// Proj GEMM (latency-optimized): C[64 x 128] tiles, grid (64, 4) = 256 CTAs.
// A = g_Av (single fp16), 2-pass (AhBh + AhBl). fp32 accum.
// 256 threads = 8 warps (2m x 4n), warp tile 32x32.
// Stage: Ah 8KB + Bh 16KB + Bl 16KB = 40KB; 3 stages = 120KB.
// ---------------------------------------------------------------------------
#define PJ_STAGE 40960
#define PJ_SMEM (3 * PJ_STAGE)     // 122880
#define PJ_OFF_B 8192
#define PJ_OFF_BL 24576

__global__ __launch_bounds__(256, 1)
void proj_mma_kernel(const float* __restrict__ x, const float* __restrict__ bp) {
    extern __shared__ char sm[];
    const uint32_t smb = smem_u32(sm);
    const int t = threadIdx.x;
    const int w = t >> 5, l = t & 31;
    const int wm = w & 1, wn = w >> 1;          // 2m x 4n
    const int gid = l >> 2, tig = l & 3;
    const int m0 = blockIdx.x * 64;
    const int n0 = blockIdx.y * 128;

    float acc[2][4][4];
#pragma unroll
    for (int i = 0; i < 2; i++)
#pragma unroll
        for (int j = 0; j < 4; j++)
#pragma unroll
            for (int c = 0; c < 4; c++) acc[i][j][c] = 0.f;

    auto issue_stage = [&](int s) {
        const int k0 = s * 64;
        const uint32_t sb = smb + (s % 3) * PJ_STAGE;
        // A: 64 rows x 64 k = 512 chunks (2 per thread)
#pragma unroll
        for (int i = 0; i < 2; i++) {
            int c = t + 256 * i;
            int row = c >> 3, cb = c & 7;
            cpasync16(sb + sw128((uint32_t)(row * 128 + cb * 16)),
                      g_Av + (size_t)(m0 + row) * EE + k0 + cb * 8);
        }
        // Bh, Bl: 128 rows x 64 k each = 1024 chunks (4 per thread)
#pragma unroll
        for (int i = 0; i < 4; i++) {
            int c = t + 256 * i;
            int row = c >> 3, cb = c & 7;
            uint32_t swo = sw128((uint32_t)(row * 128 + cb * 16));
            size_t gi = (size_t)(n0 + row) * EE + k0 + cb * 8;
            cpasync16(sb + PJ_OFF_B + swo, g_Bp_hi + gi);
            cpasync16(sb + PJ_OFF_BL + swo, g_Bp_lo + gi);
        }
        commitg();
    };

    issue_stage(0);
    issue_stage(1);

    const int li = l >> 3;
    const int lr = l & 7;

    for (int s = 0; s < 8; s++) {
        if (s < 7) waitg<1>(); else waitg<0>();
        __syncthreads();
        if (s + 2 < 8) issue_stage(s + 2);

        const uint32_t sb = smb + (s % 3) * PJ_STAGE;

#pragma unroll
        for (int kk = 0; kk < 4; kk++) {
            uint32_t ah[2][4];
#pragma unroll
            for (int mt = 0; mt < 2; mt++) {
                int row = wm * 32 + mt * 16 + (li & 1) * 8 + lr;
                int cb = kk * 2 + (li >> 1);
                uint32_t off = sw128((uint32_t)(row * 128 + cb * 16));
                ldsm4(ah[mt][0], ah[mt][1], ah[mt][2], ah[mt][3], sb + off);
            }
            uint32_t bh[2][4], bl[2][4];
#pragma unroll
            for (int p2 = 0; p2 < 2; p2++) {
                int nrow = wn * 32 + p2 * 16 + (li >> 1) * 8 + lr;
                int cb = kk * 2 + (li & 1);
                uint32_t off = sw128((uint32_t)(nrow * 128 + cb * 16));
                ldsm4(bh[p2][0], bh[p2][1], bh[p2][2], bh[p2][3],
                      sb + PJ_OFF_B + off);
                ldsm4(bl[p2][0], bl[p2][1], bl[p2][2], bl[p2][3],
                      sb + PJ_OFF_BL + off);
            }
#pragma unroll
            for (int mt = 0; mt < 2; mt++)
#pragma unroll
                for (int nt = 0; nt < 4; nt++) {
                    int p2 = nt >> 1, od = nt & 1;
                    float* c = acc[mt][nt];
                    mma16816(c, ah[mt], bh[p2][2 * od], bh[p2][2 * od + 1]);
                    mma16816(c, ah[mt], bl[p2][2 * od], bl[p2][2 * od + 1]);
                }
        }
    }

    // ---- epilogue: g_proj = acc + bp + x ----
    const int row0 = m0 + wm * 32 + gid;
#pragma unroll
    for (int mt = 0; mt < 2; mt++) {
        int rg = row0 + mt * 16;
#pragma unroll
        for (int nt = 0; nt < 4; nt++) {
            int ng = n0 + wn * 32 + nt * 8 + 2 * tig;
            float2 bpv = *(const float2*)(bp + ng);
            float2 x0 = *(const float2*)(x + (size_t)rg * EE + ng);
            float2 x1 = *(const float2*)(x + (size_t)(rg + 8) * EE + ng);
            *(float2*)(g_proj + (size_t)rg * EE + ng) =
                make_float2(acc[mt][nt][0] + bpv.x + x0.x,
                            acc[mt][nt][1] + bpv.y + x0.y);
            *(float2*)(g_proj + (size_t)(rg + 8) * EE + ng) =
                make_float2(acc[mt][nt][2] + bpv.x + x1.x,
                            acc[mt][nt][3] + bpv.y + x1.y);
        }
    }
}

// ---------------------------------------------------------------------------
// Flash attention: fp16 mma, fp32 accum. QK^T 3-pass (Q,K hi/lo);
// PV 1-pass. q-tile 128 rows, k-tiles of 64, 8 warps, 3-stage pipeline,
// warp-level masked-strip skip.
// ---------------------------------------------------------------------------
#define NEG_BIG (-1e30f)
#define SM_QH 0
#define SM_QL 16384
#define SM_STG 32768
#define STG_SZ 24576          // Kh 8K + Kl 8K + V 8K
#define OFF_KH 0
#define OFF_KL 8192
#define OFF_V 16384
#define ATTN_SMEM (SM_STG + 3 * STG_SZ)   // 106496

__global__ __launch_bounds__(256, 1)
void attn_mma_kernel() {
    extern __shared__ char sm[];
    const uint32_t smb = smem_u32(sm);
    const int t = threadIdx.x;
    const int w = t >> 5, l = t & 31;
    const int gid = l >> 2, tig = l & 3;
    const int li = l >> 3, lr = l & 7;

    const int bid = blockIdx.x;
    const int bh = bid & 15;
    const int qt = 15 - (bid >> 4);       // heavy tiles first
    const int b = bh >> 3, h = bh & 7;
    const int qs = qt * 128;
    const size_t bhoff = (size_t)bh * SS * DD;
    const int ktmax = 2 * qt + 1;

    // ---- issue Q (128x64 hi+lo); joins commit group of stage 0 ----
#pragma unroll
    for (int arr = 0; arr < 2; arr++) {
        const __half* g = arr ? g_Ql : g_Qh;
        uint32_t base = smb + (arr ? SM_QL : SM_QH);
#pragma unroll
        for (int i = 0; i < 4; i++) {
            int c = t + 256 * i;
            int row = c >> 3, cb = c & 7;
            cpasync16(base + sw128((uint32_t)(row * 128 + cb * 16)),
                      g + bhoff + (size_t)(qs + row) * DD + cb * 8);
        }
    }

    auto issue_stage = [&](int kt) {
        const uint32_t sb = smb + SM_STG + (kt % 3) * STG_SZ;
        const __half* gs[3] = {g_Kh, g_Kl, g_Vh};
        const int ks = kt * 64;
#pragma unroll
        for (int arr = 0; arr < 3; arr++) {
#pragma unroll
            for (int i = 0; i < 2; i++) {
                int c = t + 256 * i;
                int row = c >> 3, cb = c & 7;
                cpasync16(sb + arr * 8192 + sw128((uint32_t)(row * 128 + cb * 16)),
                          gs[arr] + bhoff + (size_t)(ks + row) * DD + cb * 8);
            }
        }
        commitg();
    };

    issue_stage(0);
    issue_stage(1);

    float O[8][4];
#pragma unroll
    for (int i = 0; i < 8; i++)
#pragma unroll
        for (int j = 0; j < 4; j++) O[i][j] = 0.f;
    float m0 = NEG_BIG, m1 = NEG_BIG, l0 = 0.f, l1 = 0.f;

    const int rowstrip = qs + w * 16;
    const int qg0 = rowstrip + gid;
    const int qg1 = qg0 + 8;

    for (int kt = 0; kt <= ktmax; kt++) {
        if (kt < ktmax) waitg<1>(); else waitg<0>();
        __syncthreads();
        if (kt + 2 <= ktmax) issue_stage(kt + 2);

        const uint32_t sb = smb + SM_STG + (kt % 3) * STG_SZ;
        const int ks = kt * 64;

        // warp-uniform skip: this warp's 16-row strip fully masked
        if (ks > rowstrip + 15) continue;

        // ---- S = Q K^T (3-pass fp16 hi/lo, fp32 acc) ----
        float S[8][4];
#pragma unroll
        for (int i = 0; i < 8; i++)
#pragma unroll
            for (int j = 0; j < 4; j++) S[i][j] = 0.f;

#pragma unroll
        for (int kk = 0; kk < 4; kk++) {
            uint32_t qh[4], ql[4];
            {
                int row = w * 16 + (li & 1) * 8 + lr;
                int cb = kk * 2 + (li >> 1);
                uint32_t off = sw128((uint32_t)(row * 128 + cb * 16));
                ldsm4(qh[0], qh[1], qh[2], qh[3], smb + SM_QH + off);
                ldsm4(ql[0], ql[1], ql[2], ql[3], smb + SM_QL + off);
            }
#pragma unroll
            for (int nb = 0; nb < 4; nb++) {
                uint32_t kh[4], kl[4];
                int nrow = nb * 16 + (li >> 1) * 8 + lr;
                int cb = kk * 2 + (li & 1);
                uint32_t off = sw128((uint32_t)(nrow * 128 + cb * 16));
                ldsm4(kh[0], kh[1], kh[2], kh[3], sb + OFF_KH + off);
                ldsm4(kl[0], kl[1], kl[2], kl[3], sb + OFF_KL + off);
#pragma unroll
                for (int od = 0; od < 2; od++) {
                    float* c = S[nb * 2 + od];
                    mma16816(c, qh, kh[2 * od], kh[2 * od + 1]);
                    mma16816(c, qh, kl[2 * od], kl[2 * od + 1]);
                    mma16816(c, ql, kh[2 * od], kh[2 * od + 1]);
                }
            }
        }

        // ---- causal mask ----
        if (ks + 63 > rowstrip) {
#pragma unroll
            for (int nt = 0; nt < 8; nt++) {
                int c0 = ks + nt * 8 + 2 * tig;
                if (c0 > qg0) S[nt][0] = NEG_BIG;
                if (c0 + 1 > qg0) S[nt][1] = NEG_BIG;
                if (c0 > qg1) S[nt][2] = NEG_BIG;
                if (c0 + 1 > qg1) S[nt][3] = NEG_BIG;
            }
        }

        // ---- online softmax ----
        float mx0 = NEG_BIG, mx1 = NEG_BIG;
#pragma unroll
        for (int nt = 0; nt < 8; nt++) {
            mx0 = fmaxf(mx0, fmaxf(S[nt][0], S[nt][1]));
            mx1 = fmaxf(mx1, fmaxf(S[nt][2], S[nt][3]));
        }
        mx0 = fmaxf(mx0, __shfl_xor_sync(0xffffffffu, mx0, 1));
        mx0 = fmaxf(mx0, __shfl_xor_sync(0xffffffffu, mx0, 2));
        mx1 = fmaxf(mx1, __shfl_xor_sync(0xffffffffu, mx1, 1));
        mx1 = fmaxf(mx1, __shfl_xor_sync(0xffffffffu, mx1, 2));

        float mn0 = fmaxf(m0, mx0), mn1 = fmaxf(m1, mx1);
        float sc0 = __expf(m0 - mn0), sc1 = __expf(m1 - mn1);
        float rs0 = 0.f, rs1 = 0.f;
#pragma unroll
        for (int nt = 0; nt < 8; nt++) {
            S[nt][0] = __expf(S[nt][0] - mn0);
            S[nt][1] = __expf(S[nt][1] - mn0);
            S[nt][2] = __expf(S[nt][2] - mn1);
            S[nt][3] = __expf(S[nt][3] - mn1);
            rs0 += S[nt][0] + S[nt][1];
            rs1 += S[nt][2] + S[nt][3];
        }
        rs0 += __shfl_xor_sync(0xffffffffu, rs0, 1);
        rs0 += __shfl_xor_sync(0xffffffffu, rs0, 2);
        rs1 += __shfl_xor_sync(0xffffffffu, rs1, 1);
        rs1 += __shfl_xor_sync(0xffffffffu, rs1, 2);
        l0 = l0 * sc0 + rs0;
        l1 = l1 * sc1 + rs1;
        m0 = mn0; m1 = mn1;
#pragma unroll
        for (int dt = 0; dt < 8; dt++) {
            O[dt][0] *= sc0; O[dt][1] *= sc0;
            O[dt][2] *= sc1; O[dt][3] *= sc1;
        }

        // ---- O += P V (1-pass: P fp16 x V fp16, fp32 acc) ----
#pragma unroll
        for (int kc = 0; kc < 4; kc++) {
            uint32_t pa[4];
            pa[0] = packh2(S[2 * kc][0],     S[2 * kc][1]);
            pa[1] = packh2(S[2 * kc][2],     S[2 * kc][3]);
            pa[2] = packh2(S[2 * kc + 1][0], S[2 * kc + 1][1]);
            pa[3] = packh2(S[2 * kc + 1][2], S[2 * kc + 1][3]);
#pragma unroll
            for (int db = 0; db < 4; db++) {
                uint32_t vh[4];
                int trow = kc * 16 + (li & 1) * 8 + lr;
                int dcb = (db * 16 + (li >> 1) * 8) * 2;
                uint32_t off = sw128((uint32_t)(trow * 128 + dcb));
                ldsm4t(vh[0], vh[1], vh[2], vh[3], sb + OFF_V + off);
#pragma unroll
                for (int od = 0; od < 2; od++)
                    mma16816(O[db * 2 + od], pa, vh[2 * od], vh[2 * od + 1]);
            }
        }
    }

    // ---- epilogue: vals[b, s, (7-h)*64+d] as single fp16 ----
    const float inv0 = 1.f / l0, inv1 = 1.f / l1;
    const int colbase = (HH - 1 - h) * DD;
#pragma unroll
    for (int dt = 0; dt < 8; dt++) {
        int d = dt * 8 + 2 * tig;
        size_t i0 = ((size_t)(b * SS + qg0)) * EE + colbase + d;
        size_t i1 = ((size_t)(b * SS + qg1)) * EE + colbase + d;
        *(uint32_t*)(g_Av + i0) = packh2(O[dt][0] * inv0, O[dt][1] * inv0);
        *(uint32_t*)(g_Av + i1) = packh2(O[dt][2] * inv1, O[dt][3] * inv1);
    }
}

// ---------------------------------------------------------------------------
// LayerNorm per row of 512.
// ---------------------------------------------------------------------------
__global__ void ln_kernel(const float* __restrict__ gamma,
                          const float* __restrict__ beta,
                          float* __restrict__ out) {
    const int row = blockIdx.x;
    const float* v = g_proj + (size_t)row * EE;
    const int t = threadIdx.x;

    float a0 = v[t], a1 = v[t + 256];
    float s = a0 + a1;
    float q = a0 * a0 + a1 * a1;

#pragma unroll
    for (int off = 16; off; off >>= 1) {
        s += __shfl_xor_sync(0xffffffffu, s, off);
        q += __shfl_xor_sync(0xffffffffu, q, off);
    }
    __shared__ float ss[8], sq[8];
    int w = t >> 5, lane = t & 31;
    if (lane == 0) { ss[w] = s; sq[w] = q; }
    __syncthreads();

    float S = 0.f, Q2 = 0.f;
#pragma unroll
    for (int i = 0; i < 8; i++) { S += ss[i]; Q2 += sq[i]; }

    float mu  = S * (1.f / EE);
    float var = Q2 * (1.f / EE) - mu * mu;
    float inv = rsqrtf(var + 1e-5f);

    out[(size_t)row * EE + t]       = (a0 - mu) * inv * gamma[t]       + beta[t];
    out[(size_t)row * EE + t + 256] = (a1 - mu) * inv * gamma[t + 256] + beta[t + 256];
}

// ---------------------------------------------------------------------------
extern "C" void kernel_launch(void* const* d_in, const int* in_sizes, int n_in,
                              void* d_out, int out_size) {
    const float* x     = (const float*)d_in[0];
    const float* Wq    = (const float*)d_in[1];
    const float* Wk    = (const float*)d_in[2];
    const float* Wv    = (const float*)d_in[3];
    const float* Wp    = (const float*)d_in[4];
    const float* bp    = (const float*)d_in[5];
    const float* gamma = (const float*)d_in[6];
    const float* beta  = (const float*)d_in[7];
    float* out = (float*)d_out;

    cudaFuncSetAttribute(gemm_mma_kernel, cudaFuncAttributeMaxDynamicSharedMemorySize, GEMM_SMEM);
    cudaFuncSetAttribute(proj_mma_kernel, cudaFuncAttributeMaxDynamicSharedMemorySize, PJ_SMEM);
    cudaFuncSetAttribute(attn_mma_kernel, cudaFuncAttributeMaxDynamicSharedMemorySize, ATTN_SMEM);

    prep_all_kernel<<<PREP_BLOCKS, 256>>>(Wq, Wk, Wv, Wp, x);

    gemm_mma_kernel<<<dim3(MM / 128, 12), 256, GEMM_SMEM>>>(x);
    attn_mma_kernel<<<256, 256, ATTN_SMEM>>>();
    proj_mma_kernel<<<dim3(MM / 64, 4), 256, PJ_SMEM>>>(x, bp);
    ln_kernel<<<MM, 256>>>(gamma, beta, out);
}

// round 14
// speedup vs baseline: 1.5116x; 1.5116x over previous
#include <cuda_runtime.h>
#include <cuda_fp16.h>
#include <math.h>
#include <stdint.h>

// Problem constants
#define BB 2
#define SS 2048
#define EE 512
#define HH 8
#define DD 64
#define MM (BB * SS)   // 4096 rows

// Scratch (device globals; no allocation allowed)
__device__ float g_proj[MM * EE];

// fp16 operand arrays
__device__ __align__(16) __half g_Ax_hi[MM * EE];       // x split (qkv gemm A)
__device__ __align__(16) __half g_Ax_lo[MM * EE];
__device__ __align__(16) __half g_Qh[16 * 2048 * 64];   // [bh][s][d]
__device__ __align__(16) __half g_Ql[16 * 2048 * 64];
__device__ __align__(16) __half g_Kh[16 * 2048 * 64];
__device__ __align__(16) __half g_Kl[16 * 2048 * 64];
__device__ __align__(16) __half g_Vh[16 * 2048 * 64];   // single fp16
__device__ __align__(16) __half g_Av[MM * EE];          // attention out, single fp16
__device__ __align__(16) __half g_Bqkv_hi[3 * EE * EE]; // [n=z*512+h*64+d][e]
__device__ __align__(16) __half g_Bqkv_lo[3 * EE * EE];
__device__ __align__(16) __half g_Bp_hi[EE * EE];       // [n][k] = Wp[n][k]
__device__ __align__(16) __half g_Bp_lo[EE * EE];

// ---------------------------------------------------------------------------
// helpers
// ---------------------------------------------------------------------------
__device__ __forceinline__ uint32_t smem_u32(const void* p) {
    uint32_t a;
    asm("{ .reg .u64 t; cvta.to.shared.u64 t, %1; cvt.u32.u64 %0, t; }"
        : "=r"(a) : "l"(p));
    return a;
}
__device__ __forceinline__ uint32_t sw128(uint32_t off) {
    return off ^ ((off >> 3) & 0x70);
}
__device__ __forceinline__ void cpasync16(uint32_t dst, const void* src) {
    asm volatile("cp.async.cg.shared.global [%0], [%1], 16;"
                 :: "r"(dst), "l"(src) : "memory");
}
template <int N>
__device__ __forceinline__ void waitg() {
    asm volatile("cp.async.wait_group %0;" :: "n"(N) : "memory");
}
__device__ __forceinline__ void commitg() {
    asm volatile("cp.async.commit_group;" ::: "memory");
}
__device__ __forceinline__ void ldsm4(uint32_t& r0, uint32_t& r1, uint32_t& r2,
                                      uint32_t& r3, uint32_t a) {
    asm volatile("ldmatrix.sync.aligned.m8n8.x4.shared.b16 {%0,%1,%2,%3}, [%4];"
                 : "=r"(r0), "=r"(r1), "=r"(r2), "=r"(r3) : "r"(a));
}
__device__ __forceinline__ void ldsm4t(uint32_t& r0, uint32_t& r1, uint32_t& r2,
                                       uint32_t& r3, uint32_t a) {
    asm volatile("ldmatrix.sync.aligned.m8n8.x4.trans.shared.b16 {%0,%1,%2,%3}, [%4];"
                 : "=r"(r0), "=r"(r1), "=r"(r2), "=r"(r3) : "r"(a));
}
__device__ __forceinline__ void mma16816(float* c, const uint32_t* a,
                                         uint32_t b0, uint32_t b1) {
    asm volatile(
        "mma.sync.aligned.m16n8k16.row.col.f32.f16.f16.f32 "
        "{%0,%1,%2,%3}, {%4,%5,%6,%7}, {%8,%9}, {%0,%1,%2,%3};"
        : "+f"(c[0]), "+f"(c[1]), "+f"(c[2]), "+f"(c[3])
        : "r"(a[0]), "r"(a[1]), "r"(a[2]), "r"(a[3]), "r"(b0), "r"(b1));
}
__device__ __forceinline__ uint32_t packh2(float a, float b) {
    __half ha = __float2half_rn(a), hb = __float2half_rn(b);
    return (uint32_t)__half_as_ushort(ha) |
           ((uint32_t)__half_as_ushort(hb) << 16);
}
__device__ __forceinline__ void split2h(float a, float b, uint32_t& hi, uint32_t& lo) {
    __half ha = __float2half_rn(a), hb = __float2half_rn(b);
    float ra = a - __half2float(ha), rb = b - __half2float(hb);
    hi = (uint32_t)__half_as_ushort(ha) |
         ((uint32_t)__half_as_ushort(hb) << 16);
    __half la = __float2half_rn(ra), lb = __float2half_rn(rb);
    lo = (uint32_t)__half_as_ushort(la) |
         ((uint32_t)__half_as_ushort(lb) << 16);
}

// ---------------------------------------------------------------------------
// Merged, vectorized prep: wqkv hi/lo, wp hi/lo, x hi/lo; also inits
// g_proj = x (base for the split-K proj atomics).
// ---------------------------------------------------------------------------
#define N_WQKV (3 * EE * EE)            // 786432
#define N_WP   (EE * EE)                // 262144
#define N_X    (MM * EE)                // 2097152
#define PREP_BLOCKS ((N_WQKV + N_WP + N_X) / 4 / 256)   // 3072

__global__ void prep_all_kernel(const float* __restrict__ Wq,
                                const float* __restrict__ Wk,
                                const float* __restrict__ Wv,
                                const float* __restrict__ Wp,
                                const float* __restrict__ x) {
    int idx = (blockIdx.x * 256 + threadIdx.x) * 4;
    if (idx < N_WQKV) {
        int n = idx >> 9, e0 = idx & 511;
        int z = n >> 9, h = (n >> 6) & 7, d = n & 63;
        const float* W = (z == 0) ? Wq : ((z == 1) ? Wk : Wv);
        uint32_t h0, l0, h1, l1;
        float v0 = W[((size_t)h * EE + e0 + 0) * DD + d];
        float v1 = W[((size_t)h * EE + e0 + 1) * DD + d];
        float v2 = W[((size_t)h * EE + e0 + 2) * DD + d];
        float v3 = W[((size_t)h * EE + e0 + 3) * DD + d];
        split2h(v0, v1, h0, l0);
        split2h(v2, v3, h1, l1);
        *(uint2*)(g_Bqkv_hi + idx) = make_uint2(h0, h1);
        *(uint2*)(g_Bqkv_lo + idx) = make_uint2(l0, l1);
    } else if (idx < N_WQKV + N_WP) {
        int i = idx - N_WQKV;
        float4 v = *(const float4*)(Wp + i);
        uint32_t h0, l0, h1, l1;
        split2h(v.x, v.y, h0, l0);
        split2h(v.z, v.w, h1, l1);
        *(uint2*)(g_Bp_hi + i) = make_uint2(h0, h1);
        *(uint2*)(g_Bp_lo + i) = make_uint2(l0, l1);
    } else {
        int i = idx - N_WQKV - N_WP;
        float4 v = *(const float4*)(x + i);
        uint32_t h0, l0, h1, l1;
        split2h(v.x, v.y, h0, l0);
        split2h(v.z, v.w, h1, l1);
        *(uint2*)(g_Ax_hi + i) = make_uint2(h0, h1);
        *(uint2*)(g_Ax_lo + i) = make_uint2(l0, l1);
        *(float4*)(g_proj + i) = v;          // base for proj atomics
    }
}

// ---------------------------------------------------------------------------
// QKV GEMM: C[128 x 128] tile of x[M x 512] * Wqkv[N x 512]^T. fp32 accum.
// Q/K tiles (y<8): 3-pass (AhBh+AhBl+AlBh) -> hi/lo fp16 out.
// V tiles (y>=8): 2-pass (AhBh+AlBh) -> single fp16 out.
// 256 threads = 8 warps (4m x 2n). 3-stage cp.async pipeline (k=64).
// ---------------------------------------------------------------------------
#define STAGE_BYTES 65536
#define GEMM_SMEM (3 * STAGE_BYTES)   // 196608

__global__ __launch_bounds__(256, 1)
void gemm_mma_kernel(const float* __restrict__ x) {
    extern __shared__ char sm[];
    const uint32_t smb = smem_u32(sm);
    const int t = threadIdx.x;
    const int w = t >> 5, l = t & 31;
    const int wm = w & 3, wn = w >> 2;
    const int gid = l >> 2, tig = l & 3;
    const int m0 = blockIdx.x * 128;
    const int n0 = blockIdx.y * 128;

    const bool useBl = (blockIdx.y < 8);     // pass Ah·Bl (Q/K only)

    float acc[2][8][4];
#pragma unroll
    for (int i = 0; i < 2; i++)
#pragma unroll
        for (int j = 0; j < 8; j++)
#pragma unroll
            for (int c = 0; c < 4; c++) acc[i][j][c] = 0.f;

    auto issue_stage = [&](int s) {
        const int k0 = s * 64;
        const uint32_t sb = smb + (s % 3) * STAGE_BYTES;
        const __half* gsrc[4] = {g_Ax_hi, g_Ax_lo, g_Bqkv_hi, g_Bqkv_lo};
#pragma unroll
        for (int tl = 0; tl < 4; tl++) {
            if (tl == 3 && !useBl) continue;
            const uint32_t tbase = sb + tl * 16384;
            const __half* g = gsrc[tl];
            const int rbase = (tl < 2) ? m0 : n0;
#pragma unroll
            for (int i = 0; i < 4; i++) {
                int c = t + 256 * i;
                int row = c >> 3, cb = c & 7;
                uint32_t dst = tbase + sw128((uint32_t)(row * 128 + cb * 16));
                const __half* src =
                    g + (size_t)(rbase + row) * EE + k0 + cb * 8;
                cpasync16(dst, src);
            }
        }
        commitg();
    };

    issue_stage(0);
    issue_stage(1);

    const int li = l >> 3;
    const int lr = l & 7;

    for (int s = 0; s < 8; s++) {
        if (s < 7) waitg<1>(); else waitg<0>();
        __syncthreads();
        if (s + 2 < 8) issue_stage(s + 2);

        const uint32_t sb = smb + (s % 3) * STAGE_BYTES;

#pragma unroll
        for (int kk = 0; kk < 4; kk++) {
            uint32_t ah[2][4], al[2][4];
#pragma unroll
            for (int mt = 0; mt < 2; mt++) {
                int row = wm * 32 + mt * 16 + (li & 1) * 8 + lr;
                int cb = kk * 2 + (li >> 1);
                uint32_t off = sw128((uint32_t)(row * 128 + cb * 16));
                ldsm4(ah[mt][0], ah[mt][1], ah[mt][2], ah[mt][3], sb + off);
                ldsm4(al[mt][0], al[mt][1], al[mt][2], al[mt][3],
                      sb + 16384 + off);
            }
#pragma unroll
            for (int h2 = 0; h2 < 2; h2++) {
                uint32_t bh[2][4], bl[2][4];
#pragma unroll
                for (int p2 = 0; p2 < 2; p2++) {
                    int ntb = h2 * 2 + p2;
                    int nrow = wn * 64 + ntb * 16 + (li >> 1) * 8 + lr;
                    int cb = kk * 2 + (li & 1);
                    uint32_t off = sw128((uint32_t)(nrow * 128 + cb * 16));
                    ldsm4(bh[p2][0], bh[p2][1], bh[p2][2], bh[p2][3],
                          sb + 32768 + off);
                    if (useBl)
                        ldsm4(bl[p2][0], bl[p2][1], bl[p2][2], bl[p2][3],
                              sb + 49152 + off);
                }
#pragma unroll
                for (int mt = 0; mt < 2; mt++)
#pragma unroll
                    for (int q = 0; q < 4; q++) {
                        int nt = h2 * 4 + q;
                        int p2 = q >> 1, od = q & 1;
                        float* c = acc[mt][nt];
                        mma16816(c, ah[mt], bh[p2][2 * od], bh[p2][2 * od + 1]);
                        if (useBl)
                            mma16816(c, ah[mt], bl[p2][2 * od], bl[p2][2 * od + 1]);
                        mma16816(c, al[mt], bh[p2][2 * od], bh[p2][2 * od + 1]);
                    }
            }
        }
    }

    // ---- epilogue ----
    const int row0 = m0 + wm * 32 + gid;
#pragma unroll
    for (int mt = 0; mt < 2; mt++) {
        int rg = row0 + mt * 16;
        int b = rg >> 11, sI = rg & 2047;
#pragma unroll
        for (int nt = 0; nt < 8; nt++) {
            int ng = n0 + wn * 64 + nt * 8 + 2 * tig;
            int z = ng >> 9, r9 = ng & 511;
            int h = r9 >> 6, d = r9 & 63;
            size_t base = (((size_t)(b * HH + h)) * SS + sI) * DD + d;
            if (z == 2) {
                *(uint32_t*)(g_Vh + base) =
                    packh2(acc[mt][nt][0], acc[mt][nt][1]);
                *(uint32_t*)(g_Vh + base + 8 * DD) =
                    packh2(acc[mt][nt][2], acc[mt][nt][3]);
            } else {
                __half* oh = (z == 0) ? g_Qh : g_Kh;
                __half* ol = (z == 0) ? g_Ql : g_Kl;
                uint32_t hi, lo;
                split2h(acc[mt][nt][0], acc[mt][nt][1], hi, lo);
                *(uint32_t*)(oh + base) = hi;
                *(uint32_t*)(ol + base) = lo;
                split2h(acc[mt][nt][2], acc[mt][nt][3], hi, lo);
                *(uint32_t*)(oh + base + 8 * DD) = hi;
                *(uint32_t*)(ol + base + 8 * DD) = lo;
            }
        }
    }
}

// ---------------------------------------------------------------------------
// Proj GEMM, split-K: grid (32, 4, 2). Each CTA computes a 128x128 tile
// over HALF the K range (256) in 4 pipeline stages, then atomicAdds into
// g_proj (pre-initialized to x by prep). 2-pass (AhBh + AhBl), fp32 accum.
// 256 threads = 8 warps (4m x 2n). Stage: Ah 16K + Bh 16K + Bl 16K = 48K.
// ---------------------------------------------------------------------------
#define PJS_STAGE 49152
#define PJS_SMEM (3 * PJS_STAGE)    // 147456

__global__ __launch_bounds__(256, 1)
void proj_splitk_kernel() {
    extern __shared__ char sm[];
    const uint32_t smb = smem_u32(sm);
    const int t = threadIdx.x;
    const int w = t >> 5, l = t & 31;
    const int wm = w & 3, wn = w >> 2;
    const int gid = l >> 2, tig = l & 3;
    const int m0 = blockIdx.x * 128;
    const int n0 = blockIdx.y * 128;
    const int kbase = blockIdx.z * 256;

    float acc[2][8][4];
#pragma unroll
    for (int i = 0; i < 2; i++)
#pragma unroll
        for (int j = 0; j < 8; j++)
#pragma unroll
            for (int c = 0; c < 4; c++) acc[i][j][c] = 0.f;

    auto issue_stage = [&](int s) {
        const int k0 = kbase + s * 64;
        const uint32_t sb = smb + (s % 3) * PJS_STAGE;
#pragma unroll
        for (int i = 0; i < 4; i++) {
            int c = t + 256 * i;
            int row = c >> 3, cb = c & 7;
            uint32_t swo = sw128((uint32_t)(row * 128 + cb * 16));
            cpasync16(sb + swo, g_Av + (size_t)(m0 + row) * EE + k0 + cb * 8);
            size_t gi = (size_t)(n0 + row) * EE + k0 + cb * 8;
            cpasync16(sb + 16384 + swo, g_Bp_hi + gi);
            cpasync16(sb + 32768 + swo, g_Bp_lo + gi);
        }
        commitg();
    };

    issue_stage(0);
    issue_stage(1);

    const int li = l >> 3;
    const int lr = l & 7;

    for (int s = 0; s < 4; s++) {
        if (s < 3) waitg<1>(); else waitg<0>();
        __syncthreads();
        if (s + 2 < 4) issue_stage(s + 2);

        const uint32_t sb = smb + (s % 3) * PJS_STAGE;

#pragma unroll
        for (int kk = 0; kk < 4; kk++) {
            uint32_t ah[2][4];
#pragma unroll
            for (int mt = 0; mt < 2; mt++) {
                int row = wm * 32 + mt * 16 + (li & 1) * 8 + lr;
                int cb = kk * 2 + (li >> 1);
                uint32_t off = sw128((uint32_t)(row * 128 + cb * 16));
                ldsm4(ah[mt][0], ah[mt][1], ah[mt][2], ah[mt][3], sb + off);
            }
#pragma unroll
            for (int h2 = 0; h2 < 2; h2++) {
                uint32_t bh[2][4], bl[2][4];
#pragma unroll
                for (int p2 = 0; p2 < 2; p2++) {
                    int ntb = h2 * 2 + p2;
                    int nrow = wn * 64 + ntb * 16 + (li >> 1) * 8 + lr;
                    int cb = kk * 2 + (li & 1);
                    uint32_t off = sw128((uint32_t)(nrow * 128 + cb * 16));
                    ldsm4(bh[p2][0], bh[p2][1], bh[p2][2], bh[p2][3],
                          sb + 16384 + off);
                    ldsm4(bl[p2][0], bl[p2][1], bl[p2][2], bl[p2][3],
                          sb + 32768 + off);
                }
#pragma unroll
                for (int mt = 0; mt < 2; mt++)
#pragma unroll
                    for (int q = 0; q < 4; q++) {
                        int nt = h2 * 4 + q;
                        int p2 = q >> 1, od = q & 1;
                        float* c = acc[mt][nt];
                        mma16816(c, ah[mt], bh[p2][2 * od], bh[p2][2 * od + 1]);
                        mma16816(c, ah[mt], bl[p2][2 * od], bl[p2][2 * od + 1]);
                    }
            }
        }
    }

    // ---- epilogue: atomic add into g_proj (base = x, bp added in LN) ----
    const int row0 = m0 + wm * 32 + gid;
#pragma unroll
    for (int mt = 0; mt < 2; mt++) {
        int rg = row0 + mt * 16;
#pragma unroll
        for (int nt = 0; nt < 8; nt++) {
            int ng = n0 + wn * 64 + nt * 8 + 2 * tig;
            float* p0 = g_proj + (size_t)rg * EE + ng;
            float* p1 = g_proj + (size_t)(rg + 8) * EE + ng;
            atomicAdd(p0,     acc[mt][nt][0]);
            atomicAdd(p0 + 1, acc[mt][nt][1]);
            atomicAdd(p1,     acc[mt][nt][2]);
            atomicAdd(p1 + 1, acc[mt][nt][3]);
        }
    }
}

// ---------------------------------------------------------------------------
// Flash attention: fp16 mma, fp32 accum. QK^T 3-pass (Q,K hi/lo);
// PV 1-pass. q-tile 128 rows, k-tiles of 64, 8 warps, 3-stage pipeline,
// warp-level masked-strip skip.
// ---------------------------------------------------------------------------
#define NEG_BIG (-1e30f)
#define SM_QH 0
#define SM_QL 16384
#define SM_STG 32768
#define STG_SZ 24576          // Kh 8K + Kl 8K + V 8K
#define OFF_KH 0
#define OFF_KL 8192
#define OFF_V 16384
#define ATTN_SMEM (SM_STG + 3 * STG_SZ)   // 106496

__global__ __launch_bounds__(256, 1)
void attn_mma_kernel() {
    extern __shared__ char sm[];
    const uint32_t smb = smem_u32(sm);
    const int t = threadIdx.x;
    const int w = t >> 5, l = t & 31;
    const int gid = l >> 2, tig = l & 3;
    const int li = l >> 3, lr = l & 7;

    const int bid = blockIdx.x;
    const int bh = bid & 15;
    const int qt = 15 - (bid >> 4);       // heavy tiles first
    const int b = bh >> 3, h = bh & 7;
    const int qs = qt * 128;
    const size_t bhoff = (size_t)bh * SS * DD;
    const int ktmax = 2 * qt + 1;

    // ---- issue Q (128x64 hi+lo); joins commit group of stage 0 ----
#pragma unroll
    for (int arr = 0; arr < 2; arr++) {
        const __half* g = arr ? g_Ql : g_Qh;
        uint32_t base = smb + (arr ? SM_QL : SM_QH);
#pragma unroll
        for (int i = 0; i < 4; i++) {
            int c = t + 256 * i;
            int row = c >> 3, cb = c & 7;
            cpasync16(base + sw128((uint32_t)(row * 128 + cb * 16)),
                      g + bhoff + (size_t)(qs + row) * DD + cb * 8);
        }
    }

    auto issue_stage = [&](int kt) {
        const uint32_t sb = smb + SM_STG + (kt % 3) * STG_SZ;
        const __half* gs[3] = {g_Kh, g_Kl, g_Vh};
        const int ks = kt * 64;
#pragma unroll
        for (int arr = 0; arr < 3; arr++) {
#pragma unroll
            for (int i = 0; i < 2; i++) {
                int c = t + 256 * i;
                int row = c >> 3, cb = c & 7;
                cpasync16(sb + arr * 8192 + sw128((uint32_t)(row * 128 + cb * 16)),
                          gs[arr] + bhoff + (size_t)(ks + row) * DD + cb * 8);
            }
        }
        commitg();
    };

    issue_stage(0);
    issue_stage(1);

    float O[8][4];
#pragma unroll
    for (int i = 0; i < 8; i++)
#pragma unroll
        for (int j = 0; j < 4; j++) O[i][j] = 0.f;
    float m0 = NEG_BIG, m1 = NEG_BIG, l0 = 0.f, l1 = 0.f;

    const int rowstrip = qs + w * 16;
    const int qg0 = rowstrip + gid;
    const int qg1 = qg0 + 8;

    for (int kt = 0; kt <= ktmax; kt++) {
        if (kt < ktmax) waitg<1>(); else waitg<0>();
        __syncthreads();
        if (kt + 2 <= ktmax) issue_stage(kt + 2);

        const uint32_t sb = smb + SM_STG + (kt % 3) * STG_SZ;
        const int ks = kt * 64;

        // warp-uniform skip: this warp's 16-row strip fully masked
        if (ks > rowstrip + 15) continue;

        // ---- S = Q K^T (3-pass fp16 hi/lo, fp32 acc) ----
        float S[8][4];
#pragma unroll
        for (int i = 0; i < 8; i++)
#pragma unroll
            for (int j = 0; j < 4; j++) S[i][j] = 0.f;

#pragma unroll
        for (int kk = 0; kk < 4; kk++) {
            uint32_t qh[4], ql[4];
            {
                int row = w * 16 + (li & 1) * 8 + lr;
                int cb = kk * 2 + (li >> 1);
                uint32_t off = sw128((uint32_t)(row * 128 + cb * 16));
                ldsm4(qh[0], qh[1], qh[2], qh[3], smb + SM_QH + off);
                ldsm4(ql[0], ql[1], ql[2], ql[3], smb + SM_QL + off);
            }
#pragma unroll
            for (int nb = 0; nb < 4; nb++) {
                uint32_t kh[4], kl[4];
                int nrow = nb * 16 + (li >> 1) * 8 + lr;
                int cb = kk * 2 + (li & 1);
                uint32_t off = sw128((uint32_t)(nrow * 128 + cb * 16));
                ldsm4(kh[0], kh[1], kh[2], kh[3], sb + OFF_KH + off);
                ldsm4(kl[0], kl[1], kl[2], kl[3], sb + OFF_KL + off);
#pragma unroll
                for (int od = 0; od < 2; od++) {
                    float* c = S[nb * 2 + od];
                    mma16816(c, qh, kh[2 * od], kh[2 * od + 1]);
                    mma16816(c, qh, kl[2 * od], kl[2 * od + 1]);
                    mma16816(c, ql, kh[2 * od], kh[2 * od + 1]);
                }
            }
        }

        // ---- causal mask ----
        if (ks + 63 > rowstrip) {
#pragma unroll
            for (int nt = 0; nt < 8; nt++) {
                int c0 = ks + nt * 8 + 2 * tig;
                if (c0 > qg0) S[nt][0] = NEG_BIG;
                if (c0 + 1 > qg0) S[nt][1] = NEG_BIG;
                if (c0 > qg1) S[nt][2] = NEG_BIG;
                if (c0 + 1 > qg1) S[nt][3] = NEG_BIG;
            }
        }

        // ---- online softmax ----
        float mx0 = NEG_BIG, mx1 = NEG_BIG;
#pragma unroll
        for (int nt = 0; nt < 8; nt++) {
            mx0 = fmaxf(mx0, fmaxf(S[nt][0], S[nt][1]));
            mx1 = fmaxf(mx1, fmaxf(S[nt][2], S[nt][3]));
        }
        mx0 = fmaxf(mx0, __shfl_xor_sync(0xffffffffu, mx0, 1));
        mx0 = fmaxf(mx0, __shfl_xor_sync(0xffffffffu, mx0, 2));
        mx1 = fmaxf(mx1, __shfl_xor_sync(0xffffffffu, mx1, 1));
        mx1 = fmaxf(mx1, __shfl_xor_sync(0xffffffffu, mx1, 2));

        float mn0 = fmaxf(m0, mx0), mn1 = fmaxf(m1, mx1);
        float sc0 = __expf(m0 - mn0), sc1 = __expf(m1 - mn1);
        float rs0 = 0.f, rs1 = 0.f;
#pragma unroll
        for (int nt = 0; nt < 8; nt++) {
            S[nt][0] = __expf(S[nt][0] - mn0);
            S[nt][1] = __expf(S[nt][1] - mn0);
            S[nt][2] = __expf(S[nt][2] - mn1);
            S[nt][3] = __expf(S[nt][3] - mn1);
            rs0 += S[nt][0] + S[nt][1];
            rs1 += S[nt][2] + S[nt][3];
        }
        rs0 += __shfl_xor_sync(0xffffffffu, rs0, 1);
        rs0 += __shfl_xor_sync(0xffffffffu, rs0, 2);
        rs1 += __shfl_xor_sync(0xffffffffu, rs1, 1);
        rs1 += __shfl_xor_sync(0xffffffffu, rs1, 2);
        l0 = l0 * sc0 + rs0;
        l1 = l1 * sc1 + rs1;
        m0 = mn0; m1 = mn1;
#pragma unroll
        for (int dt = 0; dt < 8; dt++) {
            O[dt][0] *= sc0; O[dt][1] *= sc0;
            O[dt][2] *= sc1; O[dt][3] *= sc1;
        }

        // ---- O += P V (1-pass: P fp16 x V fp16, fp32 acc) ----
#pragma unroll
        for (int kc = 0; kc < 4; kc++) {
            uint32_t pa[4];
            pa[0] = packh2(S[2 * kc][0],     S[2 * kc][1]);
            pa[1] = packh2(S[2 * kc][2],     S[2 * kc][3]);
            pa[2] = packh2(S[2 * kc + 1][0], S[2 * kc + 1][1]);
            pa[3] = packh2(S[2 * kc + 1][2], S[2 * kc + 1][3]);
#pragma unroll
            for (int db = 0; db < 4; db++) {
                uint32_t vh[4];
                int trow = kc * 16 + (li & 1) * 8 + lr;
                int dcb = (db * 16 + (li >> 1) * 8) * 2;
                uint32_t off = sw128((uint32_t)(trow * 128 + dcb));
                ldsm4t(vh[0], vh[1], vh[2], vh[3], sb + OFF_V + off);
#pragma unroll
                for (int od = 0; od < 2; od++)
                    mma16816(O[db * 2 + od], pa, vh[2 * od], vh[2 * od + 1]);
            }
        }
    }

    // ---- epilogue: vals[b, s, (7-h)*64+d] as single fp16 ----
    const float inv0 = 1.f / l0, inv1 = 1.f / l1;
    const int colbase = (HH - 1 - h) * DD;
#pragma unroll
    for (int dt = 0; dt < 8; dt++) {
        int d = dt * 8 + 2 * tig;
        size_t i0 = ((size_t)(b * SS + qg0)) * EE + colbase + d;
        size_t i1 = ((size_t)(b * SS + qg1)) * EE + colbase + d;
        *(uint32_t*)(g_Av + i0) = packh2(O[dt][0] * inv0, O[dt][1] * inv0);
        *(uint32_t*)(g_Av + i1) = packh2(O[dt][2] * inv1, O[dt][3] * inv1);
    }
}

// ---------------------------------------------------------------------------
// LayerNorm per row of 512. Adds bp (deferred from proj).
// ---------------------------------------------------------------------------
__global__ void ln_kernel(const float* __restrict__ bp,
                          const float* __restrict__ gamma,
                          const float* __restrict__ beta,
                          float* __restrict__ out) {
    const int row = blockIdx.x;
    const float* v = g_proj + (size_t)row * EE;
    const int t = threadIdx.x;

    float a0 = v[t] + bp[t];
    float a1 = v[t + 256] + bp[t + 256];
    float s = a0 + a1;
    float q = a0 * a0 + a1 * a1;

#pragma unroll
    for (int off = 16; off; off >>= 1) {
        s += __shfl_xor_sync(0xffffffffu, s, off);
        q += __shfl_xor_sync(0xffffffffu, q, off);
    }
    __shared__ float ss[8], sq[8];
    int w = t >> 5, lane = t & 31;
    if (lane == 0) { ss[w] = s; sq[w] = q; }
    __syncthreads();

    float S = 0.f, Q2 = 0.f;
#pragma unroll
    for (int i = 0; i < 8; i++) { S += ss[i]; Q2 += sq[i]; }

    float mu  = S * (1.f / EE);
    float var = Q2 * (1.f / EE) - mu * mu;
    float inv = rsqrtf(var + 1e-5f);

    out[(size_t)row * EE + t]       = (a0 - mu) * inv * gamma[t]       + beta[t];
    out[(size_t)row * EE + t + 256] = (a1 - mu) * inv * gamma[t + 256] + beta[t + 256];
}

// ---------------------------------------------------------------------------
extern "C" void kernel_launch(void* const* d_in, const int* in_sizes, int n_in,
                              void* d_out, int out_size) {
    const float* x     = (const float*)d_in[0];
    const float* Wq    = (const float*)d_in[1];
    const float* Wk    = (const float*)d_in[2];
    const float* Wv    = (const float*)d_in[3];
    const float* Wp    = (const float*)d_in[4];
    const float* bp    = (const float*)d_in[5];
    const float* gamma = (const float*)d_in[6];
    const float* beta  = (const float*)d_in[7];
    float* out = (float*)d_out;

    cudaFuncSetAttribute(gemm_mma_kernel, cudaFuncAttributeMaxDynamicSharedMemorySize, GEMM_SMEM);
    cudaFuncSetAttribute(proj_splitk_kernel, cudaFuncAttributeMaxDynamicSharedMemorySize, PJS_SMEM);
    cudaFuncSetAttribute(attn_mma_kernel, cudaFuncAttributeMaxDynamicSharedMemorySize, ATTN_SMEM);

    prep_all_kernel<<<PREP_BLOCKS, 256>>>(Wq, Wk, Wv, Wp, x);

    gemm_mma_kernel<<<dim3(MM / 128, 12), 256, GEMM_SMEM>>>(x);
    attn_mma_kernel<<<256, 256, ATTN_SMEM>>>();
    proj_splitk_kernel<<<dim3(MM / 128, 4, 2), 256, PJS_SMEM>>>();
    ln_kernel<<<MM, 256>>>(bp, gamma, beta, out);
}

// round 15
// speedup vs baseline: 1.5459x; 1.0227x over previous
#include <cuda_runtime.h>
#include <cuda_fp16.h>
#include <math.h>
#include <stdint.h>

// Problem constants
#define BB 2
#define SS 2048
#define EE 512
#define HH 8
#define DD 64
#define MM (BB * SS)   // 4096 rows

// Scratch (device globals; no allocation allowed)
__device__ float g_proj[MM * EE];

// fp16 operand arrays
__device__ __align__(16) __half g_Ax_hi[MM * EE];       // x split (qkv gemm A)
__device__ __align__(16) __half g_Ax_lo[MM * EE];
__device__ __align__(16) __half g_Qh[16 * 2048 * 64];   // [bh][s][d]
__device__ __align__(16) __half g_Ql[16 * 2048 * 64];
__device__ __align__(16) __half g_Kh[16 * 2048 * 64];
__device__ __align__(16) __half g_Kl[16 * 2048 * 64];
__device__ __align__(16) __half g_Vh[16 * 2048 * 64];   // single fp16
__device__ __align__(16) __half g_Av[MM * EE];          // attention out, single fp16
__device__ __align__(16) __half g_Bqkv_hi[3 * EE * EE]; // [n=z*512+h*64+d][e]
__device__ __align__(16) __half g_Bqkv_lo[3 * EE * EE];
__device__ __align__(16) __half g_Bp_hi[EE * EE];       // [n][k] = Wp[n][k]
__device__ __align__(16) __half g_Bp_lo[EE * EE];

// ---------------------------------------------------------------------------
// helpers
// ---------------------------------------------------------------------------
__device__ __forceinline__ uint32_t smem_u32(const void* p) {
    uint32_t a;
    asm("{ .reg .u64 t; cvta.to.shared.u64 t, %1; cvt.u32.u64 %0, t; }"
        : "=r"(a) : "l"(p));
    return a;
}
__device__ __forceinline__ uint32_t sw128(uint32_t off) {
    return off ^ ((off >> 3) & 0x70);
}
__device__ __forceinline__ void cpasync16(uint32_t dst, const void* src) {
    asm volatile("cp.async.cg.shared.global [%0], [%1], 16;"
                 :: "r"(dst), "l"(src) : "memory");
}
template <int N>
__device__ __forceinline__ void waitg() {
    asm volatile("cp.async.wait_group %0;" :: "n"(N) : "memory");
}
__device__ __forceinline__ void commitg() {
    asm volatile("cp.async.commit_group;" ::: "memory");
}
__device__ __forceinline__ void ldsm4(uint32_t& r0, uint32_t& r1, uint32_t& r2,
                                      uint32_t& r3, uint32_t a) {
    asm volatile("ldmatrix.sync.aligned.m8n8.x4.shared.b16 {%0,%1,%2,%3}, [%4];"
                 : "=r"(r0), "=r"(r1), "=r"(r2), "=r"(r3) : "r"(a));
}
__device__ __forceinline__ void ldsm4t(uint32_t& r0, uint32_t& r1, uint32_t& r2,
                                       uint32_t& r3, uint32_t a) {
    asm volatile("ldmatrix.sync.aligned.m8n8.x4.trans.shared.b16 {%0,%1,%2,%3}, [%4];"
                 : "=r"(r0), "=r"(r1), "=r"(r2), "=r"(r3) : "r"(a));
}
__device__ __forceinline__ void mma16816(float* c, const uint32_t* a,
                                         uint32_t b0, uint32_t b1) {
    asm volatile(
        "mma.sync.aligned.m16n8k16.row.col.f32.f16.f16.f32 "
        "{%0,%1,%2,%3}, {%4,%5,%6,%7}, {%8,%9}, {%0,%1,%2,%3};"
        : "+f"(c[0]), "+f"(c[1]), "+f"(c[2]), "+f"(c[3])
        : "r"(a[0]), "r"(a[1]), "r"(a[2]), "r"(a[3]), "r"(b0), "r"(b1));
}
__device__ __forceinline__ uint32_t packh2(float a, float b) {
    __half ha = __float2half_rn(a), hb = __float2half_rn(b);
    return (uint32_t)__half_as_ushort(ha) |
           ((uint32_t)__half_as_ushort(hb) << 16);
}
__device__ __forceinline__ void split2h(float a, float b, uint32_t& hi, uint32_t& lo) {
    __half ha = __float2half_rn(a), hb = __float2half_rn(b);
    float ra = a - __half2float(ha), rb = b - __half2float(hb);
    hi = (uint32_t)__half_as_ushort(ha) |
         ((uint32_t)__half_as_ushort(hb) << 16);
    __half la = __float2half_rn(ra), lb = __float2half_rn(rb);
    lo = (uint32_t)__half_as_ushort(la) |
         ((uint32_t)__half_as_ushort(lb) << 16);
}

// ---------------------------------------------------------------------------
// Merged, vectorized prep: wqkv hi/lo, wp hi/lo, x hi/lo; also inits
// g_proj = x + bp (base for the split-K proj atomics).
// ---------------------------------------------------------------------------
#define N_WQKV (3 * EE * EE)            // 786432
#define N_WP   (EE * EE)                // 262144
#define N_X    (MM * EE)                // 2097152
#define PREP_BLOCKS ((N_WQKV + N_WP + N_X) / 4 / 256)   // 3072

__global__ void prep_all_kernel(const float* __restrict__ Wq,
                                const float* __restrict__ Wk,
                                const float* __restrict__ Wv,
                                const float* __restrict__ Wp,
                                const float* __restrict__ x,
                                const float* __restrict__ bp) {
    int idx = (blockIdx.x * 256 + threadIdx.x) * 4;
    if (idx < N_WQKV) {
        int n = idx >> 9, e0 = idx & 511;
        int z = n >> 9, h = (n >> 6) & 7, d = n & 63;
        const float* W = (z == 0) ? Wq : ((z == 1) ? Wk : Wv);
        uint32_t h0, l0, h1, l1;
        float v0 = W[((size_t)h * EE + e0 + 0) * DD + d];
        float v1 = W[((size_t)h * EE + e0 + 1) * DD + d];
        float v2 = W[((size_t)h * EE + e0 + 2) * DD + d];
        float v3 = W[((size_t)h * EE + e0 + 3) * DD + d];
        split2h(v0, v1, h0, l0);
        split2h(v2, v3, h1, l1);
        *(uint2*)(g_Bqkv_hi + idx) = make_uint2(h0, h1);
        *(uint2*)(g_Bqkv_lo + idx) = make_uint2(l0, l1);
    } else if (idx < N_WQKV + N_WP) {
        int i = idx - N_WQKV;
        float4 v = *(const float4*)(Wp + i);
        uint32_t h0, l0, h1, l1;
        split2h(v.x, v.y, h0, l0);
        split2h(v.z, v.w, h1, l1);
        *(uint2*)(g_Bp_hi + i) = make_uint2(h0, h1);
        *(uint2*)(g_Bp_lo + i) = make_uint2(l0, l1);
    } else {
        int i = idx - N_WQKV - N_WP;
        float4 v = *(const float4*)(x + i);
        uint32_t h0, l0, h1, l1;
        split2h(v.x, v.y, h0, l0);
        split2h(v.z, v.w, h1, l1);
        *(uint2*)(g_Ax_hi + i) = make_uint2(h0, h1);
        *(uint2*)(g_Ax_lo + i) = make_uint2(l0, l1);
        float4 bpv = *(const float4*)(bp + (i & 511));
        *(float4*)(g_proj + i) =
            make_float4(v.x + bpv.x, v.y + bpv.y, v.z + bpv.z, v.w + bpv.w);
    }
}

// ---------------------------------------------------------------------------
// QKV GEMM: C[128 x 128] tile of x[M x 512] * Wqkv[N x 512]^T. fp32 accum.
// Q/K tiles (y<8): 3-pass (AhBh+AhBl+AlBh) -> hi/lo fp16 out.
// V tiles (y>=8): 1-pass (AhBh) -> single fp16 out.
// 256 threads = 8 warps (4m x 2n). 3-stage cp.async pipeline (k=64).
// ---------------------------------------------------------------------------
#define STAGE_BYTES 65536
#define GEMM_SMEM (3 * STAGE_BYTES)   // 196608

__global__ __launch_bounds__(256, 1)
void gemm_mma_kernel(const float* __restrict__ x) {
    extern __shared__ char sm[];
    const uint32_t smb = smem_u32(sm);
    const int t = threadIdx.x;
    const int w = t >> 5, l = t & 31;
    const int wm = w & 3, wn = w >> 2;
    const int gid = l >> 2, tig = l & 3;
    const int m0 = blockIdx.x * 128;
    const int n0 = blockIdx.y * 128;

    const bool isQK = (blockIdx.y < 8);      // Q/K: 3-pass; V: 1-pass

    float acc[2][8][4];
#pragma unroll
    for (int i = 0; i < 2; i++)
#pragma unroll
        for (int j = 0; j < 8; j++)
#pragma unroll
            for (int c = 0; c < 4; c++) acc[i][j][c] = 0.f;

    auto issue_stage = [&](int s) {
        const int k0 = s * 64;
        const uint32_t sb = smb + (s % 3) * STAGE_BYTES;
        const __half* gsrc[4] = {g_Ax_hi, g_Ax_lo, g_Bqkv_hi, g_Bqkv_lo};
#pragma unroll
        for (int tl = 0; tl < 4; tl++) {
            if ((tl == 1 || tl == 3) && !isQK) continue;
            const uint32_t tbase = sb + tl * 16384;
            const __half* g = gsrc[tl];
            const int rbase = (tl < 2) ? m0 : n0;
#pragma unroll
            for (int i = 0; i < 4; i++) {
                int c = t + 256 * i;
                int row = c >> 3, cb = c & 7;
                uint32_t dst = tbase + sw128((uint32_t)(row * 128 + cb * 16));
                const __half* src =
                    g + (size_t)(rbase + row) * EE + k0 + cb * 8;
                cpasync16(dst, src);
            }
        }
        commitg();
    };

    issue_stage(0);
    issue_stage(1);

    const int li = l >> 3;
    const int lr = l & 7;

    for (int s = 0; s < 8; s++) {
        if (s < 7) waitg<1>(); else waitg<0>();
        __syncthreads();
        if (s + 2 < 8) issue_stage(s + 2);

        const uint32_t sb = smb + (s % 3) * STAGE_BYTES;

#pragma unroll
        for (int kk = 0; kk < 4; kk++) {
            uint32_t ah[2][4], al[2][4];
#pragma unroll
            for (int mt = 0; mt < 2; mt++) {
                int row = wm * 32 + mt * 16 + (li & 1) * 8 + lr;
                int cb = kk * 2 + (li >> 1);
                uint32_t off = sw128((uint32_t)(row * 128 + cb * 16));
                ldsm4(ah[mt][0], ah[mt][1], ah[mt][2], ah[mt][3], sb + off);
                if (isQK)
                    ldsm4(al[mt][0], al[mt][1], al[mt][2], al[mt][3],
                          sb + 16384 + off);
            }
#pragma unroll
            for (int h2 = 0; h2 < 2; h2++) {
                uint32_t bh[2][4], bl[2][4];
#pragma unroll
                for (int p2 = 0; p2 < 2; p2++) {
                    int ntb = h2 * 2 + p2;
                    int nrow = wn * 64 + ntb * 16 + (li >> 1) * 8 + lr;
                    int cb = kk * 2 + (li & 1);
                    uint32_t off = sw128((uint32_t)(nrow * 128 + cb * 16));
                    ldsm4(bh[p2][0], bh[p2][1], bh[p2][2], bh[p2][3],
                          sb + 32768 + off);
                    if (isQK)
                        ldsm4(bl[p2][0], bl[p2][1], bl[p2][2], bl[p2][3],
                              sb + 49152 + off);
                }
#pragma unroll
                for (int mt = 0; mt < 2; mt++)
#pragma unroll
                    for (int q = 0; q < 4; q++) {
                        int nt = h2 * 4 + q;
                        int p2 = q >> 1, od = q & 1;
                        float* c = acc[mt][nt];
                        mma16816(c, ah[mt], bh[p2][2 * od], bh[p2][2 * od + 1]);
                        if (isQK) {
                            mma16816(c, ah[mt], bl[p2][2 * od], bl[p2][2 * od + 1]);
                            mma16816(c, al[mt], bh[p2][2 * od], bh[p2][2 * od + 1]);
                        }
                    }
            }
        }
    }

    // ---- epilogue ----
    const int row0 = m0 + wm * 32 + gid;
#pragma unroll
    for (int mt = 0; mt < 2; mt++) {
        int rg = row0 + mt * 16;
        int b = rg >> 11, sI = rg & 2047;
#pragma unroll
        for (int nt = 0; nt < 8; nt++) {
            int ng = n0 + wn * 64 + nt * 8 + 2 * tig;
            int z = ng >> 9, r9 = ng & 511;
            int h = r9 >> 6, d = r9 & 63;
            size_t base = (((size_t)(b * HH + h)) * SS + sI) * DD + d;
            if (z == 2) {
                *(uint32_t*)(g_Vh + base) =
                    packh2(acc[mt][nt][0], acc[mt][nt][1]);
                *(uint32_t*)(g_Vh + base + 8 * DD) =
                    packh2(acc[mt][nt][2], acc[mt][nt][3]);
            } else {
                __half* oh = (z == 0) ? g_Qh : g_Kh;
                __half* ol = (z == 0) ? g_Ql : g_Kl;
                uint32_t hi, lo;
                split2h(acc[mt][nt][0], acc[mt][nt][1], hi, lo);
                *(uint32_t*)(oh + base) = hi;
                *(uint32_t*)(ol + base) = lo;
                split2h(acc[mt][nt][2], acc[mt][nt][3], hi, lo);
                *(uint32_t*)(oh + base + 8 * DD) = hi;
                *(uint32_t*)(ol + base + 8 * DD) = lo;
            }
        }
    }
}

// ---------------------------------------------------------------------------
// Proj GEMM, split-K: grid (32, 4, 2). Each CTA computes a 128x128 tile
// over HALF the K range (256) in 4 pipeline stages, then atomicAdds into
// g_proj (pre-initialized to x + bp by prep). 2-pass (AhBh + AhBl).
// ---------------------------------------------------------------------------
#define PJS_STAGE 49152
#define PJS_SMEM (3 * PJS_STAGE)    // 147456

__global__ __launch_bounds__(256, 1)
void proj_splitk_kernel() {
    extern __shared__ char sm[];
    const uint32_t smb = smem_u32(sm);
    const int t = threadIdx.x;
    const int w = t >> 5, l = t & 31;
    const int wm = w & 3, wn = w >> 2;
    const int gid = l >> 2, tig = l & 3;
    const int m0 = blockIdx.x * 128;
    const int n0 = blockIdx.y * 128;
    const int kbase = blockIdx.z * 256;

    float acc[2][8][4];
#pragma unroll
    for (int i = 0; i < 2; i++)
#pragma unroll
        for (int j = 0; j < 8; j++)
#pragma unroll
            for (int c = 0; c < 4; c++) acc[i][j][c] = 0.f;

    auto issue_stage = [&](int s) {
        const int k0 = kbase + s * 64;
        const uint32_t sb = smb + (s % 3) * PJS_STAGE;
#pragma unroll
        for (int i = 0; i < 4; i++) {
            int c = t + 256 * i;
            int row = c >> 3, cb = c & 7;
            uint32_t swo = sw128((uint32_t)(row * 128 + cb * 16));
            cpasync16(sb + swo, g_Av + (size_t)(m0 + row) * EE + k0 + cb * 8);
            size_t gi = (size_t)(n0 + row) * EE + k0 + cb * 8;
            cpasync16(sb + 16384 + swo, g_Bp_hi + gi);
            cpasync16(sb + 32768 + swo, g_Bp_lo + gi);
        }
        commitg();
    };

    issue_stage(0);
    issue_stage(1);

    const int li = l >> 3;
    const int lr = l & 7;

    for (int s = 0; s < 4; s++) {
        if (s < 3) waitg<1>(); else waitg<0>();
        __syncthreads();
        if (s + 2 < 4) issue_stage(s + 2);

        const uint32_t sb = smb + (s % 3) * PJS_STAGE;

#pragma unroll
        for (int kk = 0; kk < 4; kk++) {
            uint32_t ah[2][4];
#pragma unroll
            for (int mt = 0; mt < 2; mt++) {
                int row = wm * 32 + mt * 16 + (li & 1) * 8 + lr;
                int cb = kk * 2 + (li >> 1);
                uint32_t off = sw128((uint32_t)(row * 128 + cb * 16));
                ldsm4(ah[mt][0], ah[mt][1], ah[mt][2], ah[mt][3], sb + off);
            }
#pragma unroll
            for (int h2 = 0; h2 < 2; h2++) {
                uint32_t bh[2][4], bl[2][4];
#pragma unroll
                for (int p2 = 0; p2 < 2; p2++) {
                    int ntb = h2 * 2 + p2;
                    int nrow = wn * 64 + ntb * 16 + (li >> 1) * 8 + lr;
                    int cb = kk * 2 + (li & 1);
                    uint32_t off = sw128((uint32_t)(nrow * 128 + cb * 16));
                    ldsm4(bh[p2][0], bh[p2][1], bh[p2][2], bh[p2][3],
                          sb + 16384 + off);
                    ldsm4(bl[p2][0], bl[p2][1], bl[p2][2], bl[p2][3],
                          sb + 32768 + off);
                }
#pragma unroll
                for (int mt = 0; mt < 2; mt++)
#pragma unroll
                    for (int q = 0; q < 4; q++) {
                        int nt = h2 * 4 + q;
                        int p2 = q >> 1, od = q & 1;
                        float* c = acc[mt][nt];
                        mma16816(c, ah[mt], bh[p2][2 * od], bh[p2][2 * od + 1]);
                        mma16816(c, ah[mt], bl[p2][2 * od], bl[p2][2 * od + 1]);
                    }
            }
        }
    }

    // ---- epilogue: atomic add into g_proj ----
    const int row0 = m0 + wm * 32 + gid;
#pragma unroll
    for (int mt = 0; mt < 2; mt++) {
        int rg = row0 + mt * 16;
#pragma unroll
        for (int nt = 0; nt < 8; nt++) {
            int ng = n0 + wn * 64 + nt * 8 + 2 * tig;
            float* p0 = g_proj + (size_t)rg * EE + ng;
            float* p1 = g_proj + (size_t)(rg + 8) * EE + ng;
            atomicAdd(p0,     acc[mt][nt][0]);
            atomicAdd(p0 + 1, acc[mt][nt][1]);
            atomicAdd(p1,     acc[mt][nt][2]);
            atomicAdd(p1 + 1, acc[mt][nt][3]);
        }
    }
}

// ---------------------------------------------------------------------------
// Flash attention: fp16 mma, fp32 accum. QK^T 3-pass (Q,K hi/lo);
// PV 1-pass. q-tile 128 rows, k-tiles of 64, 8 warps, 3-stage pipeline,
// warp-level masked-strip skip.
// ---------------------------------------------------------------------------
#define NEG_BIG (-1e30f)
#define SM_QH 0
#define SM_QL 16384
#define SM_STG 32768
#define STG_SZ 24576          // Kh 8K + Kl 8K + V 8K
#define OFF_KH 0
#define OFF_KL 8192
#define OFF_V 16384
#define ATTN_SMEM (SM_STG + 3 * STG_SZ)   // 106496

__global__ __launch_bounds__(256, 1)
void attn_mma_kernel() {
    extern __shared__ char sm[];
    const uint32_t smb = smem_u32(sm);
    const int t = threadIdx.x;
    const int w = t >> 5, l = t & 31;
    const int gid = l >> 2, tig = l & 3;
    const int li = l >> 3, lr = l & 7;

    const int bid = blockIdx.x;
    const int bh = bid & 15;
    const int qt = 15 - (bid >> 4);       // heavy tiles first
    const int b = bh >> 3, h = bh & 7;
    const int qs = qt * 128;
    const size_t bhoff = (size_t)bh * SS * DD;
    const int ktmax = 2 * qt + 1;

    // ---- issue Q (128x64 hi+lo); joins commit group of stage 0 ----
#pragma unroll
    for (int arr = 0; arr < 2; arr++) {
        const __half* g = arr ? g_Ql : g_Qh;
        uint32_t base = smb + (arr ? SM_QL : SM_QH);
#pragma unroll
        for (int i = 0; i < 4; i++) {
            int c = t + 256 * i;
            int row = c >> 3, cb = c & 7;
            cpasync16(base + sw128((uint32_t)(row * 128 + cb * 16)),
                      g + bhoff + (size_t)(qs + row) * DD + cb * 8);
        }
    }

    auto issue_stage = [&](int kt) {
        const uint32_t sb = smb + SM_STG + (kt % 3) * STG_SZ;
        const __half* gs[3] = {g_Kh, g_Kl, g_Vh};
        const int ks = kt * 64;
#pragma unroll
        for (int arr = 0; arr < 3; arr++) {
#pragma unroll
            for (int i = 0; i < 2; i++) {
                int c = t + 256 * i;
                int row = c >> 3, cb = c & 7;
                cpasync16(sb + arr * 8192 + sw128((uint32_t)(row * 128 + cb * 16)),
                          gs[arr] + bhoff + (size_t)(ks + row) * DD + cb * 8);
            }
        }
        commitg();
    };

    issue_stage(0);
    issue_stage(1);

    float O[8][4];
#pragma unroll
    for (int i = 0; i < 8; i++)
#pragma unroll
        for (int j = 0; j < 4; j++) O[i][j] = 0.f;
    float m0 = NEG_BIG, m1 = NEG_BIG, l0 = 0.f, l1 = 0.f;

    const int rowstrip = qs + w * 16;
    const int qg0 = rowstrip + gid;
    const int qg1 = qg0 + 8;

    for (int kt = 0; kt <= ktmax; kt++) {
        if (kt < ktmax) waitg<1>(); else waitg<0>();
        __syncthreads();
        if (kt + 2 <= ktmax) issue_stage(kt + 2);

        const uint32_t sb = smb + SM_STG + (kt % 3) * STG_SZ;
        const int ks = kt * 64;

        // warp-uniform skip: this warp's 16-row strip fully masked
        if (ks > rowstrip + 15) continue;

        // ---- S = Q K^T (3-pass fp16 hi/lo, fp32 acc) ----
        float S[8][4];
#pragma unroll
        for (int i = 0; i < 8; i++)
#pragma unroll
            for (int j = 0; j < 4; j++) S[i][j] = 0.f;

#pragma unroll
        for (int kk = 0; kk < 4; kk++) {
            uint32_t qh[4], ql[4];
            {
                int row = w * 16 + (li & 1) * 8 + lr;
                int cb = kk * 2 + (li >> 1);
                uint32_t off = sw128((uint32_t)(row * 128 + cb * 16));
                ldsm4(qh[0], qh[1], qh[2], qh[3], smb + SM_QH + off);
                ldsm4(ql[0], ql[1], ql[2], ql[3], smb + SM_QL + off);
            }
#pragma unroll
            for (int nb = 0; nb < 4; nb++) {
                uint32_t kh[4], kl[4];
                int nrow = nb * 16 + (li >> 1) * 8 + lr;
                int cb = kk * 2 + (li & 1);
                uint32_t off = sw128((uint32_t)(nrow * 128 + cb * 16));
                ldsm4(kh[0], kh[1], kh[2], kh[3], sb + OFF_KH + off);
                ldsm4(kl[0], kl[1], kl[2], kl[3], sb + OFF_KL + off);
#pragma unroll
                for (int od = 0; od < 2; od++) {
                    float* c = S[nb * 2 + od];
                    mma16816(c, qh, kh[2 * od], kh[2 * od + 1]);
                    mma16816(c, qh, kl[2 * od], kl[2 * od + 1]);
                    mma16816(c, ql, kh[2 * od], kh[2 * od + 1]);
                }
            }
        }

        // ---- causal mask ----
        if (ks + 63 > rowstrip) {
#pragma unroll
            for (int nt = 0; nt < 8; nt++) {
                int c0 = ks + nt * 8 + 2 * tig;
                if (c0 > qg0) S[nt][0] = NEG_BIG;
                if (c0 + 1 > qg0) S[nt][1] = NEG_BIG;
                if (c0 > qg1) S[nt][2] = NEG_BIG;
                if (c0 + 1 > qg1) S[nt][3] = NEG_BIG;
            }
        }

        // ---- online softmax ----
        float mx0 = NEG_BIG, mx1 = NEG_BIG;
#pragma unroll
        for (int nt = 0; nt < 8; nt++) {
            mx0 = fmaxf(mx0, fmaxf(S[nt][0], S[nt][1]));
            mx1 = fmaxf(mx1, fmaxf(S[nt][2], S[nt][3]));
        }
        mx0 = fmaxf(mx0, __shfl_xor_sync(0xffffffffu, mx0, 1));
        mx0 = fmaxf(mx0, __shfl_xor_sync(0xffffffffu, mx0, 2));
        mx1 = fmaxf(mx1, __shfl_xor_sync(0xffffffffu, mx1, 1));
        mx1 = fmaxf(mx1, __shfl_xor_sync(0xffffffffu, mx1, 2));

        float mn0 = fmaxf(m0, mx0), mn1 = fmaxf(m1, mx1);
        float sc0 = __expf(m0 - mn0), sc1 = __expf(m1 - mn1);
        float rs0 = 0.f, rs1 = 0.f;
#pragma unroll
        for (int nt = 0; nt < 8; nt++) {
            S[nt][0] = __expf(S[nt][0] - mn0);
            S[nt][1] = __expf(S[nt][1] - mn0);
            S[nt][2] = __expf(S[nt][2] - mn1);
            S[nt][3] = __expf(S[nt][3] - mn1);
            rs0 += S[nt][0] + S[nt][1];
            rs1 += S[nt][2] + S[nt][3];
        }
        rs0 += __shfl_xor_sync(0xffffffffu, rs0, 1);
        rs0 += __shfl_xor_sync(0xffffffffu, rs0, 2);
        rs1 += __shfl_xor_sync(0xffffffffu, rs1, 1);
        rs1 += __shfl_xor_sync(0xffffffffu, rs1, 2);
        l0 = l0 * sc0 + rs0;
        l1 = l1 * sc1 + rs1;
        m0 = mn0; m1 = mn1;
#pragma unroll
        for (int dt = 0; dt < 8; dt++) {
            O[dt][0] *= sc0; O[dt][1] *= sc0;
            O[dt][2] *= sc1; O[dt][3] *= sc1;
        }

        // ---- O += P V (1-pass: P fp16 x V fp16, fp32 acc) ----
#pragma unroll
        for (int kc = 0; kc < 4; kc++) {
            uint32_t pa[4];
            pa[0] = packh2(S[2 * kc][0],     S[2 * kc][1]);
            pa[1] = packh2(S[2 * kc][2],     S[2 * kc][3]);
            pa[2] = packh2(S[2 * kc + 1][0], S[2 * kc + 1][1]);
            pa[3] = packh2(S[2 * kc + 1][2], S[2 * kc + 1][3]);
#pragma unroll
            for (int db = 0; db < 4; db++) {
                uint32_t vh[4];
                int trow = kc * 16 + (li & 1) * 8 + lr;
                int dcb = (db * 16 + (li >> 1) * 8) * 2;
                uint32_t off = sw128((uint32_t)(trow * 128 + dcb));
                ldsm4t(vh[0], vh[1], vh[2], vh[3], sb + OFF_V + off);
#pragma unroll
                for (int od = 0; od < 2; od++)
                    mma16816(O[db * 2 + od], pa, vh[2 * od], vh[2 * od + 1]);
            }
        }
    }

    // ---- epilogue: vals[b, s, (7-h)*64+d] as single fp16 ----
    const float inv0 = 1.f / l0, inv1 = 1.f / l1;
    const int colbase = (HH - 1 - h) * DD;
#pragma unroll
    for (int dt = 0; dt < 8; dt++) {
        int d = dt * 8 + 2 * tig;
        size_t i0 = ((size_t)(b * SS + qg0)) * EE + colbase + d;
        size_t i1 = ((size_t)(b * SS + qg1)) * EE + colbase + d;
        *(uint32_t*)(g_Av + i0) = packh2(O[dt][0] * inv0, O[dt][1] * inv0);
        *(uint32_t*)(g_Av + i1) = packh2(O[dt][2] * inv1, O[dt][3] * inv1);
    }
}

// ---------------------------------------------------------------------------
// LayerNorm, vectorized: 2 rows per 256-thread block, float4 per thread.
// ---------------------------------------------------------------------------
__global__ void ln_kernel(const float* __restrict__ gamma,
                          const float* __restrict__ beta,
                          float* __restrict__ out) {
    const int t = threadIdx.x;
    const int rsub = t >> 7;                 // 0..1 (row within block)
    const int tr = t & 127;                  // thread within row
    const int row = blockIdx.x * 2 + rsub;
    const int e0 = tr * 4;

    float4 a = *(const float4*)(g_proj + (size_t)row * EE + e0);
    float s = a.x + a.y + a.z + a.w;
    float q = a.x * a.x + a.y * a.y + a.z * a.z + a.w * a.w;

#pragma unroll
    for (int off = 16; off; off >>= 1) {
        s += __shfl_xor_sync(0xffffffffu, s, off);
        q += __shfl_xor_sync(0xffffffffu, q, off);
    }
    __shared__ float ss[2][4], sq[2][4];
    int wir = (t >> 5) & 3;                  // warp within row
    if ((t & 31) == 0) { ss[rsub][wir] = s; sq[rsub][wir] = q; }
    __syncthreads();

    float S = ss[rsub][0] + ss[rsub][1] + ss[rsub][2] + ss[rsub][3];
    float Q2 = sq[rsub][0] + sq[rsub][1] + sq[rsub][2] + sq[rsub][3];

    float mu  = S * (1.f / EE);
    float var = Q2 * (1.f / EE) - mu * mu;
    float inv = rsqrtf(var + 1e-5f);

    float4 g = *(const float4*)(gamma + e0);
    float4 be = *(const float4*)(beta + e0);
    float4 o;
    o.x = (a.x - mu) * inv * g.x + be.x;
    o.y = (a.y - mu) * inv * g.y + be.y;
    o.z = (a.z - mu) * inv * g.z + be.z;
    o.w = (a.w - mu) * inv * g.w + be.w;
    *(float4*)(out + (size_t)row * EE + e0) = o;
}

// ---------------------------------------------------------------------------
extern "C" void kernel_launch(void* const* d_in, const int* in_sizes, int n_in,
                              void* d_out, int out_size) {
    const float* x     = (const float*)d_in[0];
    const float* Wq    = (const float*)d_in[1];
    const float* Wk    = (const float*)d_in[2];
    const float* Wv    = (const float*)d_in[3];
    const float* Wp    = (const float*)d_in[4];
    const float* bp    = (const float*)d_in[5];
    const float* gamma = (const float*)d_in[6];
    const float* beta  = (const float*)d_in[7];
    float* out = (float*)d_out;

    cudaFuncSetAttribute(gemm_mma_kernel, cudaFuncAttributeMaxDynamicSharedMemorySize, GEMM_SMEM);
    cudaFuncSetAttribute(proj_splitk_kernel, cudaFuncAttributeMaxDynamicSharedMemorySize, PJS_SMEM);
    cudaFuncSetAttribute(attn_mma_kernel, cudaFuncAttributeMaxDynamicSharedMemorySize, ATTN_SMEM);

    prep_all_kernel<<<PREP_BLOCKS, 256>>>(Wq, Wk, Wv, Wp, x, bp);

    gemm_mma_kernel<<<dim3(MM / 128, 12), 256, GEMM_SMEM>>>(x);
    attn_mma_kernel<<<256, 256, ATTN_SMEM>>>();
    proj_splitk_kernel<<<dim3(MM / 128, 4, 2), 256, PJS_SMEM>>>();
    ln_kernel<<<MM / 2, 256>>>(gamma, beta, out);
}

// round 16
// speedup vs baseline: 1.5988x; 1.0342x over previous
#include <cuda_runtime.h>
#include <cuda_fp16.h>
#include <math.h>
#include <stdint.h>

// Problem constants
#define BB 2
#define SS 2048
#define EE 512
#define HH 8
#define DD 64
#define MM (BB * SS)   // 4096 rows

// Scratch (device globals; no allocation allowed)
__device__ float g_proj[MM * EE];

// fp16 operand arrays
__device__ __align__(16) __half g_Ax_hi[MM * EE];       // x split (qkv gemm A)
__device__ __align__(16) __half g_Ax_lo[MM * EE];
__device__ __align__(16) __half g_Qh[16 * 2048 * 64];   // [bh][s][d]
__device__ __align__(16) __half g_Ql[16 * 2048 * 64];
__device__ __align__(16) __half g_Kh[16 * 2048 * 64];
__device__ __align__(16) __half g_Kl[16 * 2048 * 64];
__device__ __align__(16) __half g_Vh[16 * 2048 * 64];   // single fp16
__device__ __align__(16) __half g_Av[MM * EE];          // attention out, single fp16
__device__ __align__(16) __half g_Bqkv_hi[3 * EE * EE]; // [n=z*512+h*64+d][e]
__device__ __align__(16) __half g_Bqkv_lo[3 * EE * EE];
__device__ __align__(16) __half g_Bp_hi[EE * EE];       // [n][k] = Wp[n][k]

// ---------------------------------------------------------------------------
// helpers
// ---------------------------------------------------------------------------
__device__ __forceinline__ uint32_t smem_u32(const void* p) {
    uint32_t a;
    asm("{ .reg .u64 t; cvta.to.shared.u64 t, %1; cvt.u32.u64 %0, t; }"
        : "=r"(a) : "l"(p));
    return a;
}
__device__ __forceinline__ uint32_t sw128(uint32_t off) {
    return off ^ ((off >> 3) & 0x70);
}
__device__ __forceinline__ void cpasync16(uint32_t dst, const void* src) {
    asm volatile("cp.async.cg.shared.global [%0], [%1], 16;"
                 :: "r"(dst), "l"(src) : "memory");
}
template <int N>
__device__ __forceinline__ void waitg() {
    asm volatile("cp.async.wait_group %0;" :: "n"(N) : "memory");
}
__device__ __forceinline__ void commitg() {
    asm volatile("cp.async.commit_group;" ::: "memory");
}
__device__ __forceinline__ void ldsm4(uint32_t& r0, uint32_t& r1, uint32_t& r2,
                                      uint32_t& r3, uint32_t a) {
    asm volatile("ldmatrix.sync.aligned.m8n8.x4.shared.b16 {%0,%1,%2,%3}, [%4];"
                 : "=r"(r0), "=r"(r1), "=r"(r2), "=r"(r3) : "r"(a));
}
__device__ __forceinline__ void ldsm4t(uint32_t& r0, uint32_t& r1, uint32_t& r2,
                                       uint32_t& r3, uint32_t a) {
    asm volatile("ldmatrix.sync.aligned.m8n8.x4.trans.shared.b16 {%0,%1,%2,%3}, [%4];"
                 : "=r"(r0), "=r"(r1), "=r"(r2), "=r"(r3) : "r"(a));
}
__device__ __forceinline__ void mma16816(float* c, const uint32_t* a,
                                         uint32_t b0, uint32_t b1) {
    asm volatile(
        "mma.sync.aligned.m16n8k16.row.col.f32.f16.f16.f32 "
        "{%0,%1,%2,%3}, {%4,%5,%6,%7}, {%8,%9}, {%0,%1,%2,%3};"
        : "+f"(c[0]), "+f"(c[1]), "+f"(c[2]), "+f"(c[3])
        : "r"(a[0]), "r"(a[1]), "r"(a[2]), "r"(a[3]), "r"(b0), "r"(b1));
}
__device__ __forceinline__ uint32_t packh2(float a, float b) {
    __half ha = __float2half_rn(a), hb = __float2half_rn(b);
    return (uint32_t)__half_as_ushort(ha) |
           ((uint32_t)__half_as_ushort(hb) << 16);
}
__device__ __forceinline__ void split2h(float a, float b, uint32_t& hi, uint32_t& lo) {
    __half ha = __float2half_rn(a), hb = __float2half_rn(b);
    float ra = a - __half2float(ha), rb = b - __half2float(hb);
    hi = (uint32_t)__half_as_ushort(ha) |
         ((uint32_t)__half_as_ushort(hb) << 16);
    __half la = __float2half_rn(ra), lb = __float2half_rn(rb);
    lo = (uint32_t)__half_as_ushort(la) |
         ((uint32_t)__half_as_ushort(lb) << 16);
}

// ---------------------------------------------------------------------------
// Merged, vectorized prep: wqkv hi/lo, wp hi, x hi/lo; also inits
// g_proj = x + bp (base for the split-K proj atomics).
// ---------------------------------------------------------------------------
#define N_WQKV (3 * EE * EE)            // 786432
#define N_WP   (EE * EE)                // 262144
#define N_X    (MM * EE)                // 2097152
#define PREP_BLOCKS ((N_WQKV + N_WP + N_X) / 4 / 256)   // 3072

__global__ void prep_all_kernel(const float* __restrict__ Wq,
                                const float* __restrict__ Wk,
                                const float* __restrict__ Wv,
                                const float* __restrict__ Wp,
                                const float* __restrict__ x,
                                const float* __restrict__ bp) {
    int idx = (blockIdx.x * 256 + threadIdx.x) * 4;
    if (idx < N_WQKV) {
        int n = idx >> 9, e0 = idx & 511;
        int z = n >> 9, h = (n >> 6) & 7, d = n & 63;
        const float* W = (z == 0) ? Wq : ((z == 1) ? Wk : Wv);
        uint32_t h0, l0, h1, l1;
        float v0 = W[((size_t)h * EE + e0 + 0) * DD + d];
        float v1 = W[((size_t)h * EE + e0 + 1) * DD + d];
        float v2 = W[((size_t)h * EE + e0 + 2) * DD + d];
        float v3 = W[((size_t)h * EE + e0 + 3) * DD + d];
        split2h(v0, v1, h0, l0);
        split2h(v2, v3, h1, l1);
        *(uint2*)(g_Bqkv_hi + idx) = make_uint2(h0, h1);
        *(uint2*)(g_Bqkv_lo + idx) = make_uint2(l0, l1);
    } else if (idx < N_WQKV + N_WP) {
        int i = idx - N_WQKV;
        float4 v = *(const float4*)(Wp + i);
        uint32_t h0 = packh2(v.x, v.y);
        uint32_t h1 = packh2(v.z, v.w);
        *(uint2*)(g_Bp_hi + i) = make_uint2(h0, h1);
    } else {
        int i = idx - N_WQKV - N_WP;
        float4 v = *(const float4*)(x + i);
        uint32_t h0, l0, h1, l1;
        split2h(v.x, v.y, h0, l0);
        split2h(v.z, v.w, h1, l1);
        *(uint2*)(g_Ax_hi + i) = make_uint2(h0, h1);
        *(uint2*)(g_Ax_lo + i) = make_uint2(l0, l1);
        float4 bpv = *(const float4*)(bp + (i & 511));
        *(float4*)(g_proj + i) =
            make_float4(v.x + bpv.x, v.y + bpv.y, v.z + bpv.z, v.w + bpv.w);
    }
}

// ---------------------------------------------------------------------------
// QKV GEMM: C[128 x 128] tile of x[M x 512] * Wqkv[N x 512]^T. fp32 accum.
// Q/K tiles (y<8): 3-pass (AhBh+AhBl+AlBh) -> hi/lo fp16 out.
// V tiles (y>=8): 1-pass (AhBh) -> single fp16 out.
// 256 threads = 8 warps (4m x 2n). 3-stage cp.async pipeline (k=64).
// ---------------------------------------------------------------------------
#define STAGE_BYTES 65536
#define GEMM_SMEM (3 * STAGE_BYTES)   // 196608

__global__ __launch_bounds__(256, 1)
void gemm_mma_kernel(const float* __restrict__ x) {
    extern __shared__ char sm[];
    const uint32_t smb = smem_u32(sm);
    const int t = threadIdx.x;
    const int w = t >> 5, l = t & 31;
    const int wm = w & 3, wn = w >> 2;
    const int gid = l >> 2, tig = l & 3;
    const int m0 = blockIdx.x * 128;
    const int n0 = blockIdx.y * 128;

    const bool isQK = (blockIdx.y < 8);      // Q/K: 3-pass; V: 1-pass

    float acc[2][8][4];
#pragma unroll
    for (int i = 0; i < 2; i++)
#pragma unroll
        for (int j = 0; j < 8; j++)
#pragma unroll
            for (int c = 0; c < 4; c++) acc[i][j][c] = 0.f;

    auto issue_stage = [&](int s) {
        const int k0 = s * 64;
        const uint32_t sb = smb + (s % 3) * STAGE_BYTES;
        const __half* gsrc[4] = {g_Ax_hi, g_Ax_lo, g_Bqkv_hi, g_Bqkv_lo};
#pragma unroll
        for (int tl = 0; tl < 4; tl++) {
            if ((tl == 1 || tl == 3) && !isQK) continue;
            const uint32_t tbase = sb + tl * 16384;
            const __half* g = gsrc[tl];
            const int rbase = (tl < 2) ? m0 : n0;
#pragma unroll
            for (int i = 0; i < 4; i++) {
                int c = t + 256 * i;
                int row = c >> 3, cb = c & 7;
                uint32_t dst = tbase + sw128((uint32_t)(row * 128 + cb * 16));
                const __half* src =
                    g + (size_t)(rbase + row) * EE + k0 + cb * 8;
                cpasync16(dst, src);
            }
        }
        commitg();
    };

    issue_stage(0);
    issue_stage(1);

    const int li = l >> 3;
    const int lr = l & 7;

    for (int s = 0; s < 8; s++) {
        if (s < 7) waitg<1>(); else waitg<0>();
        __syncthreads();
        if (s + 2 < 8) issue_stage(s + 2);

        const uint32_t sb = smb + (s % 3) * STAGE_BYTES;

#pragma unroll
        for (int kk = 0; kk < 4; kk++) {
            uint32_t ah[2][4], al[2][4];
#pragma unroll
            for (int mt = 0; mt < 2; mt++) {
                int row = wm * 32 + mt * 16 + (li & 1) * 8 + lr;
                int cb = kk * 2 + (li >> 1);
                uint32_t off = sw128((uint32_t)(row * 128 + cb * 16));
                ldsm4(ah[mt][0], ah[mt][1], ah[mt][2], ah[mt][3], sb + off);
                if (isQK)
                    ldsm4(al[mt][0], al[mt][1], al[mt][2], al[mt][3],
                          sb + 16384 + off);
            }
#pragma unroll
            for (int h2 = 0; h2 < 2; h2++) {
                uint32_t bh[2][4], bl[2][4];
#pragma unroll
                for (int p2 = 0; p2 < 2; p2++) {
                    int ntb = h2 * 2 + p2;
                    int nrow = wn * 64 + ntb * 16 + (li >> 1) * 8 + lr;
                    int cb = kk * 2 + (li & 1);
                    uint32_t off = sw128((uint32_t)(nrow * 128 + cb * 16));
                    ldsm4(bh[p2][0], bh[p2][1], bh[p2][2], bh[p2][3],
                          sb + 32768 + off);
                    if (isQK)
                        ldsm4(bl[p2][0], bl[p2][1], bl[p2][2], bl[p2][3],
                              sb + 49152 + off);
                }
#pragma unroll
                for (int mt = 0; mt < 2; mt++)
#pragma unroll
                    for (int q = 0; q < 4; q++) {
                        int nt = h2 * 4 + q;
                        int p2 = q >> 1, od = q & 1;
                        float* c = acc[mt][nt];
                        mma16816(c, ah[mt], bh[p2][2 * od], bh[p2][2 * od + 1]);
                        if (isQK) {
                            mma16816(c, ah[mt], bl[p2][2 * od], bl[p2][2 * od + 1]);
                            mma16816(c, al[mt], bh[p2][2 * od], bh[p2][2 * od + 1]);
                        }
                    }
            }
        }
    }

    // ---- epilogue ----
    const int row0 = m0 + wm * 32 + gid;
#pragma unroll
    for (int mt = 0; mt < 2; mt++) {
        int rg = row0 + mt * 16;
        int b = rg >> 11, sI = rg & 2047;
#pragma unroll
        for (int nt = 0; nt < 8; nt++) {
            int ng = n0 + wn * 64 + nt * 8 + 2 * tig;
            int z = ng >> 9, r9 = ng & 511;
            int h = r9 >> 6, d = r9 & 63;
            size_t base = (((size_t)(b * HH + h)) * SS + sI) * DD + d;
            if (z == 2) {
                *(uint32_t*)(g_Vh + base) =
                    packh2(acc[mt][nt][0], acc[mt][nt][1]);
                *(uint32_t*)(g_Vh + base + 8 * DD) =
                    packh2(acc[mt][nt][2], acc[mt][nt][3]);
            } else {
                __half* oh = (z == 0) ? g_Qh : g_Kh;
                __half* ol = (z == 0) ? g_Ql : g_Kl;
                uint32_t hi, lo;
                split2h(acc[mt][nt][0], acc[mt][nt][1], hi, lo);
                *(uint32_t*)(oh + base) = hi;
                *(uint32_t*)(ol + base) = lo;
                split2h(acc[mt][nt][2], acc[mt][nt][3], hi, lo);
                *(uint32_t*)(oh + base + 8 * DD) = hi;
                *(uint32_t*)(ol + base + 8 * DD) = lo;
            }
        }
    }
}

// ---------------------------------------------------------------------------
// Proj GEMM, split-K, 1-pass (Av fp16 x Wp-hi): grid (32, 4, 2). Each CTA
// computes a 128x128 tile over half the K range (4 stages of k=64), then
// atomicAdds into g_proj (pre-initialized to x + bp by prep).
// Stage: Ah 16K + Bh 16K = 32KB; 3 stages = 96KB.
// ---------------------------------------------------------------------------
#define PJS_STAGE 32768
#define PJS_SMEM (3 * PJS_STAGE)    // 98304

__global__ __launch_bounds__(256, 1)
void proj_splitk_kernel() {
    extern __shared__ char sm[];
    const uint32_t smb = smem_u32(sm);
    const int t = threadIdx.x;
    const int w = t >> 5, l = t & 31;
    const int wm = w & 3, wn = w >> 2;
    const int gid = l >> 2, tig = l & 3;
    const int m0 = blockIdx.x * 128;
    const int n0 = blockIdx.y * 128;
    const int kbase = blockIdx.z * 256;

    float acc[2][8][4];
#pragma unroll
    for (int i = 0; i < 2; i++)
#pragma unroll
        for (int j = 0; j < 8; j++)
#pragma unroll
            for (int c = 0; c < 4; c++) acc[i][j][c] = 0.f;

    auto issue_stage = [&](int s) {
        const int k0 = kbase + s * 64;
        const uint32_t sb = smb + (s % 3) * PJS_STAGE;
#pragma unroll
        for (int i = 0; i < 4; i++) {
            int c = t + 256 * i;
            int row = c >> 3, cb = c & 7;
            uint32_t swo = sw128((uint32_t)(row * 128 + cb * 16));
            cpasync16(sb + swo, g_Av + (size_t)(m0 + row) * EE + k0 + cb * 8);
            cpasync16(sb + 16384 + swo,
                      g_Bp_hi + (size_t)(n0 + row) * EE + k0 + cb * 8);
        }
        commitg();
    };

    issue_stage(0);
    issue_stage(1);

    const int li = l >> 3;
    const int lr = l & 7;

    for (int s = 0; s < 4; s++) {
        if (s < 3) waitg<1>(); else waitg<0>();
        __syncthreads();
        if (s + 2 < 4) issue_stage(s + 2);

        const uint32_t sb = smb + (s % 3) * PJS_STAGE;

#pragma unroll
        for (int kk = 0; kk < 4; kk++) {
            uint32_t ah[2][4];
#pragma unroll
            for (int mt = 0; mt < 2; mt++) {
                int row = wm * 32 + mt * 16 + (li & 1) * 8 + lr;
                int cb = kk * 2 + (li >> 1);
                uint32_t off = sw128((uint32_t)(row * 128 + cb * 16));
                ldsm4(ah[mt][0], ah[mt][1], ah[mt][2], ah[mt][3], sb + off);
            }
#pragma unroll
            for (int h2 = 0; h2 < 2; h2++) {
                uint32_t bh[2][4];
#pragma unroll
                for (int p2 = 0; p2 < 2; p2++) {
                    int ntb = h2 * 2 + p2;
                    int nrow = wn * 64 + ntb * 16 + (li >> 1) * 8 + lr;
                    int cb = kk * 2 + (li & 1);
                    uint32_t off = sw128((uint32_t)(nrow * 128 + cb * 16));
                    ldsm4(bh[p2][0], bh[p2][1], bh[p2][2], bh[p2][3],
                          sb + 16384 + off);
                }
#pragma unroll
                for (int mt = 0; mt < 2; mt++)
#pragma unroll
                    for (int q = 0; q < 4; q++) {
                        int nt = h2 * 4 + q;
                        int p2 = q >> 1, od = q & 1;
                        mma16816(acc[mt][nt], ah[mt],
                                 bh[p2][2 * od], bh[p2][2 * od + 1]);
                    }
            }
        }
    }

    // ---- epilogue: atomic add into g_proj ----
    const int row0 = m0 + wm * 32 + gid;
#pragma unroll
    for (int mt = 0; mt < 2; mt++) {
        int rg = row0 + mt * 16;
#pragma unroll
        for (int nt = 0; nt < 8; nt++) {
            int ng = n0 + wn * 64 + nt * 8 + 2 * tig;
            float* p0 = g_proj + (size_t)rg * EE + ng;
            float* p1 = g_proj + (size_t)(rg + 8) * EE + ng;
            atomicAdd(p0,     acc[mt][nt][0]);
            atomicAdd(p0 + 1, acc[mt][nt][1]);
            atomicAdd(p1,     acc[mt][nt][2]);
            atomicAdd(p1 + 1, acc[mt][nt][3]);
        }
    }
}

// ---------------------------------------------------------------------------
// Flash attention: fp16 mma, fp32 accum. QK^T 3-pass (Q,K hi/lo);
// PV 1-pass. q-tile 128 rows, k-tiles of 64, 8 warps, 3-stage pipeline,
// warp-level masked-strip skip.
// ---------------------------------------------------------------------------
#define NEG_BIG (-1e30f)
#define SM_QH 0
#define SM_QL 16384
#define SM_STG 32768
#define STG_SZ 24576          // Kh 8K + Kl 8K + V 8K
#define OFF_KH 0
#define OFF_KL 8192
#define OFF_V 16384
#define ATTN_SMEM (SM_STG + 3 * STG_SZ)   // 106496

__global__ __launch_bounds__(256, 1)
void attn_mma_kernel() {
    extern __shared__ char sm[];
    const uint32_t smb = smem_u32(sm);
    const int t = threadIdx.x;
    const int w = t >> 5, l = t & 31;
    const int gid = l >> 2, tig = l & 3;
    const int li = l >> 3, lr = l & 7;

    const int bid = blockIdx.x;
    const int bh = bid & 15;
    const int qt = 15 - (bid >> 4);       // heavy tiles first
    const int b = bh >> 3, h = bh & 7;
    const int qs = qt * 128;
    const size_t bhoff = (size_t)bh * SS * DD;
    const int ktmax = 2 * qt + 1;

    // ---- issue Q (128x64 hi+lo); joins commit group of stage 0 ----
#pragma unroll
    for (int arr = 0; arr < 2; arr++) {
        const __half* g = arr ? g_Ql : g_Qh;
        uint32_t base = smb + (arr ? SM_QL : SM_QH);
#pragma unroll
        for (int i = 0; i < 4; i++) {
            int c = t + 256 * i;
            int row = c >> 3, cb = c & 7;
            cpasync16(base + sw128((uint32_t)(row * 128 + cb * 16)),
                      g + bhoff + (size_t)(qs + row) * DD + cb * 8);
        }
    }

    auto issue_stage = [&](int kt) {
        const uint32_t sb = smb + SM_STG + (kt % 3) * STG_SZ;
        const __half* gs[3] = {g_Kh, g_Kl, g_Vh};
        const int ks = kt * 64;
#pragma unroll
        for (int arr = 0; arr < 3; arr++) {
#pragma unroll
            for (int i = 0; i < 2; i++) {
                int c = t + 256 * i;
                int row = c >> 3, cb = c & 7;
                cpasync16(sb + arr * 8192 + sw128((uint32_t)(row * 128 + cb * 16)),
                          gs[arr] + bhoff + (size_t)(ks + row) * DD + cb * 8);
            }
        }
        commitg();
    };

    issue_stage(0);
    issue_stage(1);

    float O[8][4];
#pragma unroll
    for (int i = 0; i < 8; i++)
#pragma unroll
        for (int j = 0; j < 4; j++) O[i][j] = 0.f;
    float m0 = NEG_BIG, m1 = NEG_BIG, l0 = 0.f, l1 = 0.f;

    const int rowstrip = qs + w * 16;
    const int qg0 = rowstrip + gid;
    const int qg1 = qg0 + 8;

    for (int kt = 0; kt <= ktmax; kt++) {
        if (kt < ktmax) waitg<1>(); else waitg<0>();
        __syncthreads();
        if (kt + 2 <= ktmax) issue_stage(kt + 2);

        const uint32_t sb = smb + SM_STG + (kt % 3) * STG_SZ;
        const int ks = kt * 64;

        // warp-uniform skip: this warp's 16-row strip fully masked
        if (ks > rowstrip + 15) continue;

        // ---- S = Q K^T (3-pass fp16 hi/lo, fp32 acc) ----
        float S[8][4];
#pragma unroll
        for (int i = 0; i < 8; i++)
#pragma unroll
            for (int j = 0; j < 4; j++) S[i][j] = 0.f;

#pragma unroll
        for (int kk = 0; kk < 4; kk++) {
            uint32_t qh[4], ql[4];
            {
                int row = w * 16 + (li & 1) * 8 + lr;
                int cb = kk * 2 + (li >> 1);
                uint32_t off = sw128((uint32_t)(row * 128 + cb * 16));
                ldsm4(qh[0], qh[1], qh[2], qh[3], smb + SM_QH + off);
                ldsm4(ql[0], ql[1], ql[2], ql[3], smb + SM_QL + off);
            }
#pragma unroll
            for (int nb = 0; nb < 4; nb++) {
                uint32_t kh[4], kl[4];
                int nrow = nb * 16 + (li >> 1) * 8 + lr;
                int cb = kk * 2 + (li & 1);
                uint32_t off = sw128((uint32_t)(nrow * 128 + cb * 16));
                ldsm4(kh[0], kh[1], kh[2], kh[3], sb + OFF_KH + off);
                ldsm4(kl[0], kl[1], kl[2], kl[3], sb + OFF_KL + off);
#pragma unroll
                for (int od = 0; od < 2; od++) {
                    float* c = S[nb * 2 + od];
                    mma16816(c, qh, kh[2 * od], kh[2 * od + 1]);
                    mma16816(c, qh, kl[2 * od], kl[2 * od + 1]);
                    mma16816(c, ql, kh[2 * od], kh[2 * od + 1]);
                }
            }
        }

        // ---- causal mask ----
        if (ks + 63 > rowstrip) {
#pragma unroll
            for (int nt = 0; nt < 8; nt++) {
                int c0 = ks + nt * 8 + 2 * tig;
                if (c0 > qg0) S[nt][0] = NEG_BIG;
                if (c0 + 1 > qg0) S[nt][1] = NEG_BIG;
                if (c0 > qg1) S[nt][2] = NEG_BIG;
                if (c0 + 1 > qg1) S[nt][3] = NEG_BIG;
            }
        }

        // ---- online softmax ----
        float mx0 = NEG_BIG, mx1 = NEG_BIG;
#pragma unroll
        for (int nt = 0; nt < 8; nt++) {
            mx0 = fmaxf(mx0, fmaxf(S[nt][0], S[nt][1]));
            mx1 = fmaxf(mx1, fmaxf(S[nt][2], S[nt][3]));
        }
        mx0 = fmaxf(mx0, __shfl_xor_sync(0xffffffffu, mx0, 1));
        mx0 = fmaxf(mx0, __shfl_xor_sync(0xffffffffu, mx0, 2));
        mx1 = fmaxf(mx1, __shfl_xor_sync(0xffffffffu, mx1, 1));
        mx1 = fmaxf(mx1, __shfl_xor_sync(0xffffffffu, mx1, 2));

        float mn0 = fmaxf(m0, mx0), mn1 = fmaxf(m1, mx1);
        float sc0 = __expf(m0 - mn0), sc1 = __expf(m1 - mn1);
        float rs0 = 0.f, rs1 = 0.f;
#pragma unroll
        for (int nt = 0; nt < 8; nt++) {
            S[nt][0] = __expf(S[nt][0] - mn0);
            S[nt][1] = __expf(S[nt][1] - mn0);
            S[nt][2] = __expf(S[nt][2] - mn1);
            S[nt][3] = __expf(S[nt][3] - mn1);
            rs0 += S[nt][0] + S[nt][1];
            rs1 += S[nt][2] + S[nt][3];
        }
        rs0 += __shfl_xor_sync(0xffffffffu, rs0, 1);
        rs0 += __shfl_xor_sync(0xffffffffu, rs0, 2);
        rs1 += __shfl_xor_sync(0xffffffffu, rs1, 1);
        rs1 += __shfl_xor_sync(0xffffffffu, rs1, 2);
        l0 = l0 * sc0 + rs0;
        l1 = l1 * sc1 + rs1;
        m0 = mn0; m1 = mn1;
#pragma unroll
        for (int dt = 0; dt < 8; dt++) {
            O[dt][0] *= sc0; O[dt][1] *= sc0;
            O[dt][2] *= sc1; O[dt][3] *= sc1;
        }

        // ---- O += P V (1-pass: P fp16 x V fp16, fp32 acc) ----
#pragma unroll
        for (int kc = 0; kc < 4; kc++) {
            uint32_t pa[4];
            pa[0] = packh2(S[2 * kc][0],     S[2 * kc][1]);
            pa[1] = packh2(S[2 * kc][2],     S[2 * kc][3]);
            pa[2] = packh2(S[2 * kc + 1][0], S[2 * kc + 1][1]);
            pa[3] = packh2(S[2 * kc + 1][2], S[2 * kc + 1][3]);
#pragma unroll
            for (int db = 0; db < 4; db++) {
                uint32_t vh[4];
                int trow = kc * 16 + (li & 1) * 8 + lr;
                int dcb = (db * 16 + (li >> 1) * 8) * 2;
                uint32_t off = sw128((uint32_t)(trow * 128 + dcb));
                ldsm4t(vh[0], vh[1], vh[2], vh[3], sb + OFF_V + off);
#pragma unroll
                for (int od = 0; od < 2; od++)
                    mma16816(O[db * 2 + od], pa, vh[2 * od], vh[2 * od + 1]);
            }
        }
    }

    // ---- epilogue: vals[b, s, (7-h)*64+d] as single fp16 ----
    const float inv0 = 1.f / l0, inv1 = 1.f / l1;
    const int colbase = (HH - 1 - h) * DD;
#pragma unroll
    for (int dt = 0; dt < 8; dt++) {
        int d = dt * 8 + 2 * tig;
        size_t i0 = ((size_t)(b * SS + qg0)) * EE + colbase + d;
        size_t i1 = ((size_t)(b * SS + qg1)) * EE + colbase + d;
        *(uint32_t*)(g_Av + i0) = packh2(O[dt][0] * inv0, O[dt][1] * inv0);
        *(uint32_t*)(g_Av + i1) = packh2(O[dt][2] * inv1, O[dt][3] * inv1);
    }
}

// ---------------------------------------------------------------------------
// LayerNorm, vectorized: 2 rows per 256-thread block, float4 per thread.
// ---------------------------------------------------------------------------
__global__ void ln_kernel(const float* __restrict__ gamma,
                          const float* __restrict__ beta,
                          float* __restrict__ out) {
    const int t = threadIdx.x;
    const int rsub = t >> 7;
    const int tr = t & 127;
    const int row = blockIdx.x * 2 + rsub;
    const int e0 = tr * 4;

    float4 a = *(const float4*)(g_proj + (size_t)row * EE + e0);
    float s = a.x + a.y + a.z + a.w;
    float q = a.x * a.x + a.y * a.y + a.z * a.z + a.w * a.w;

#pragma unroll
    for (int off = 16; off; off >>= 1) {
        s += __shfl_xor_sync(0xffffffffu, s, off);
        q += __shfl_xor_sync(0xffffffffu, q, off);
    }
    __shared__ float ss[2][4], sq[2][4];
    int wir = (t >> 5) & 3;
    if ((t & 31) == 0) { ss[rsub][wir] = s; sq[rsub][wir] = q; }
    __syncthreads();

    float S = ss[rsub][0] + ss[rsub][1] + ss[rsub][2] + ss[rsub][3];
    float Q2 = sq[rsub][0] + sq[rsub][1] + sq[rsub][2] + sq[rsub][3];

    float mu  = S * (1.f / EE);
    float var = Q2 * (1.f / EE) - mu * mu;
    float inv = rsqrtf(var + 1e-5f);

    float4 g = *(const float4*)(gamma + e0);
    float4 be = *(const float4*)(beta + e0);
    float4 o;
    o.x = (a.x - mu) * inv * g.x + be.x;
    o.y = (a.y - mu) * inv * g.y + be.y;
    o.z = (a.z - mu) * inv * g.z + be.z;
    o.w = (a.w - mu) * inv * g.w + be.w;
    *(float4*)(out + (size_t)row * EE + e0) = o;
}

// ---------------------------------------------------------------------------
extern "C" void kernel_launch(void* const* d_in, const int* in_sizes, int n_in,
                              void* d_out, int out_size) {
    const float* x     = (const float*)d_in[0];
    const float* Wq    = (const float*)d_in[1];
    const float* Wk    = (const float*)d_in[2];
    const float* Wv    = (const float*)d_in[3];
    const float* Wp    = (const float*)d_in[4];
    const float* bp    = (const float*)d_in[5];
    const float* gamma = (const float*)d_in[6];
    const float* beta  = (const float*)d_in[7];
    float* out = (float*)d_out;

    cudaFuncSetAttribute(gemm_mma_kernel, cudaFuncAttributeMaxDynamicSharedMemorySize, GEMM_SMEM);
    cudaFuncSetAttribute(proj_splitk_kernel, cudaFuncAttributeMaxDynamicSharedMemorySize, PJS_SMEM);
    cudaFuncSetAttribute(attn_mma_kernel, cudaFuncAttributeMaxDynamicSharedMemorySize, ATTN_SMEM);

    prep_all_kernel<<<PREP_BLOCKS, 256>>>(Wq, Wk, Wv, Wp, x, bp);

    gemm_mma_kernel<<<dim3(MM / 128, 12), 256, GEMM_SMEM>>>(x);
    attn_mma_kernel<<<256, 256, ATTN_SMEM>>>();
    proj_splitk_kernel<<<dim3(MM / 128, 4, 2), 256, PJS_SMEM>>>();
    ln_kernel<<<MM / 2, 256>>>(gamma, beta, out);
}

// round 17
// speedup vs baseline: 1.6185x; 1.0123x over previous
#include <cuda_runtime.h>
#include <cuda_fp16.h>
#include <math.h>
#include <stdint.h>

// Problem constants
#define BB 2
#define SS 2048
#define EE 512
#define HH 8
#define DD 64
#define MM (BB * SS)   // 4096 rows

// Scratch (device globals; no allocation allowed)
__device__ float g_p0[MM * EE];      // proj partial, kz=0
__device__ float g_p1[MM * EE];      // proj partial, kz=1

// fp16 operand arrays
__device__ __align__(16) __half g_Ax_hi[MM * EE];       // x split (qkv gemm A)
__device__ __align__(16) __half g_Ax_lo[MM * EE];
__device__ __align__(16) __half g_Qh[16 * 2048 * 64];   // [bh][s][d]
__device__ __align__(16) __half g_Ql[16 * 2048 * 64];
__device__ __align__(16) __half g_Kh[16 * 2048 * 64];
__device__ __align__(16) __half g_Kl[16 * 2048 * 64];
__device__ __align__(16) __half g_Vh[16 * 2048 * 64];   // single fp16
__device__ __align__(16) __half g_Av[MM * EE];          // attention out, single fp16
__device__ __align__(16) __half g_Bqkv_hi[3 * EE * EE]; // [n=z*512+h*64+d][e]
__device__ __align__(16) __half g_Bqkv_lo[3 * EE * EE];
__device__ __align__(16) __half g_Bp_hi[EE * EE];       // [n][k] = Wp[n][k]

// ---------------------------------------------------------------------------
// helpers
// ---------------------------------------------------------------------------
__device__ __forceinline__ uint32_t smem_u32(const void* p) {
    uint32_t a;
    asm("{ .reg .u64 t; cvta.to.shared.u64 t, %1; cvt.u32.u64 %0, t; }"
        : "=r"(a) : "l"(p));
    return a;
}
__device__ __forceinline__ uint32_t sw128(uint32_t off) {
    return off ^ ((off >> 3) & 0x70);
}
__device__ __forceinline__ void cpasync16(uint32_t dst, const void* src) {
    asm volatile("cp.async.cg.shared.global [%0], [%1], 16;"
                 :: "r"(dst), "l"(src) : "memory");
}
template <int N>
__device__ __forceinline__ void waitg() {
    asm volatile("cp.async.wait_group %0;" :: "n"(N) : "memory");
}
__device__ __forceinline__ void commitg() {
    asm volatile("cp.async.commit_group;" ::: "memory");
}
__device__ __forceinline__ void ldsm4(uint32_t& r0, uint32_t& r1, uint32_t& r2,
                                      uint32_t& r3, uint32_t a) {
    asm volatile("ldmatrix.sync.aligned.m8n8.x4.shared.b16 {%0,%1,%2,%3}, [%4];"
                 : "=r"(r0), "=r"(r1), "=r"(r2), "=r"(r3) : "r"(a));
}
__device__ __forceinline__ void ldsm4t(uint32_t& r0, uint32_t& r1, uint32_t& r2,
                                       uint32_t& r3, uint32_t a) {
    asm volatile("ldmatrix.sync.aligned.m8n8.x4.trans.shared.b16 {%0,%1,%2,%3}, [%4];"
                 : "=r"(r0), "=r"(r1), "=r"(r2), "=r"(r3) : "r"(a));
}
__device__ __forceinline__ void mma16816(float* c, const uint32_t* a,
                                         uint32_t b0, uint32_t b1) {
    asm volatile(
        "mma.sync.aligned.m16n8k16.row.col.f32.f16.f16.f32 "
        "{%0,%1,%2,%3}, {%4,%5,%6,%7}, {%8,%9}, {%0,%1,%2,%3};"
        : "+f"(c[0]), "+f"(c[1]), "+f"(c[2]), "+f"(c[3])
        : "r"(a[0]), "r"(a[1]), "r"(a[2]), "r"(a[3]), "r"(b0), "r"(b1));
}
__device__ __forceinline__ uint32_t packh2(float a, float b) {
    __half ha = __float2half_rn(a), hb = __float2half_rn(b);
    return (uint32_t)__half_as_ushort(ha) |
           ((uint32_t)__half_as_ushort(hb) << 16);
}
__device__ __forceinline__ void split2h(float a, float b, uint32_t& hi, uint32_t& lo) {
    __half ha = __float2half_rn(a), hb = __float2half_rn(b);
    float ra = a - __half2float(ha), rb = b - __half2float(hb);
    hi = (uint32_t)__half_as_ushort(ha) |
         ((uint32_t)__half_as_ushort(hb) << 16);
    __half la = __float2half_rn(ra), lb = __float2half_rn(rb);
    lo = (uint32_t)__half_as_ushort(la) |
         ((uint32_t)__half_as_ushort(lb) << 16);
}

// ---------------------------------------------------------------------------
// Merged, vectorized prep: wqkv hi/lo, wp hi, x hi/lo — ONE launch.
// ---------------------------------------------------------------------------
#define N_WQKV (3 * EE * EE)            // 786432
#define N_WP   (EE * EE)                // 262144
#define N_X    (MM * EE)                // 2097152
#define PREP_BLOCKS ((N_WQKV + N_WP + N_X) / 4 / 256)   // 3072

__global__ void prep_all_kernel(const float* __restrict__ Wq,
                                const float* __restrict__ Wk,
                                const float* __restrict__ Wv,
                                const float* __restrict__ Wp,
                                const float* __restrict__ x) {
    int idx = (blockIdx.x * 256 + threadIdx.x) * 4;
    if (idx < N_WQKV) {
        int n = idx >> 9, e0 = idx & 511;
        int z = n >> 9, h = (n >> 6) & 7, d = n & 63;
        const float* W = (z == 0) ? Wq : ((z == 1) ? Wk : Wv);
        uint32_t h0, l0, h1, l1;
        float v0 = W[((size_t)h * EE + e0 + 0) * DD + d];
        float v1 = W[((size_t)h * EE + e0 + 1) * DD + d];
        float v2 = W[((size_t)h * EE + e0 + 2) * DD + d];
        float v3 = W[((size_t)h * EE + e0 + 3) * DD + d];
        split2h(v0, v1, h0, l0);
        split2h(v2, v3, h1, l1);
        *(uint2*)(g_Bqkv_hi + idx) = make_uint2(h0, h1);
        *(uint2*)(g_Bqkv_lo + idx) = make_uint2(l0, l1);
    } else if (idx < N_WQKV + N_WP) {
        int i = idx - N_WQKV;
        float4 v = *(const float4*)(Wp + i);
        uint32_t h0 = packh2(v.x, v.y);
        uint32_t h1 = packh2(v.z, v.w);
        *(uint2*)(g_Bp_hi + i) = make_uint2(h0, h1);
    } else {
        int i = idx - N_WQKV - N_WP;
        float4 v = *(const float4*)(x + i);
        uint32_t h0, l0, h1, l1;
        split2h(v.x, v.y, h0, l0);
        split2h(v.z, v.w, h1, l1);
        *(uint2*)(g_Ax_hi + i) = make_uint2(h0, h1);
        *(uint2*)(g_Ax_lo + i) = make_uint2(l0, l1);
    }
}

// ---------------------------------------------------------------------------
// QKV GEMM: C[128 x 128] tile of x[M x 512] * Wqkv[N x 512]^T. fp32 accum.
// Q/K tiles (y<8): 3-pass (AhBh+AhBl+AlBh) -> hi/lo fp16 out.
// V tiles (y>=8): 1-pass (AhBh) -> single fp16 out.
// 256 threads = 8 warps (4m x 2n). 3-stage cp.async pipeline (k=64).
// ---------------------------------------------------------------------------
#define STAGE_BYTES 65536
#define GEMM_SMEM (3 * STAGE_BYTES)   // 196608

__global__ __launch_bounds__(256, 1)
void gemm_mma_kernel(const float* __restrict__ x) {
    extern __shared__ char sm[];
    const uint32_t smb = smem_u32(sm);
    const int t = threadIdx.x;
    const int w = t >> 5, l = t & 31;
    const int wm = w & 3, wn = w >> 2;
    const int gid = l >> 2, tig = l & 3;
    const int m0 = blockIdx.x * 128;
    const int n0 = blockIdx.y * 128;

    const bool isQK = (blockIdx.y < 8);      // Q/K: 3-pass; V: 1-pass

    float acc[2][8][4];
#pragma unroll
    for (int i = 0; i < 2; i++)
#pragma unroll
        for (int j = 0; j < 8; j++)
#pragma unroll
            for (int c = 0; c < 4; c++) acc[i][j][c] = 0.f;

    auto issue_stage = [&](int s) {
        const int k0 = s * 64;
        const uint32_t sb = smb + (s % 3) * STAGE_BYTES;
        const __half* gsrc[4] = {g_Ax_hi, g_Ax_lo, g_Bqkv_hi, g_Bqkv_lo};
#pragma unroll
        for (int tl = 0; tl < 4; tl++) {
            if ((tl == 1 || tl == 3) && !isQK) continue;
            const uint32_t tbase = sb + tl * 16384;
            const __half* g = gsrc[tl];
            const int rbase = (tl < 2) ? m0 : n0;
#pragma unroll
            for (int i = 0; i < 4; i++) {
                int c = t + 256 * i;
                int row = c >> 3, cb = c & 7;
                uint32_t dst = tbase + sw128((uint32_t)(row * 128 + cb * 16));
                const __half* src =
                    g + (size_t)(rbase + row) * EE + k0 + cb * 8;
                cpasync16(dst, src);
            }
        }
        commitg();
    };

    issue_stage(0);
    issue_stage(1);

    const int li = l >> 3;
    const int lr = l & 7;

    for (int s = 0; s < 8; s++) {
        if (s < 7) waitg<1>(); else waitg<0>();
        __syncthreads();
        if (s + 2 < 8) issue_stage(s + 2);

        const uint32_t sb = smb + (s % 3) * STAGE_BYTES;

#pragma unroll
        for (int kk = 0; kk < 4; kk++) {
            uint32_t ah[2][4], al[2][4];
#pragma unroll
            for (int mt = 0; mt < 2; mt++) {
                int row = wm * 32 + mt * 16 + (li & 1) * 8 + lr;
                int cb = kk * 2 + (li >> 1);
                uint32_t off = sw128((uint32_t)(row * 128 + cb * 16));
                ldsm4(ah[mt][0], ah[mt][1], ah[mt][2], ah[mt][3], sb + off);
                if (isQK)
                    ldsm4(al[mt][0], al[mt][1], al[mt][2], al[mt][3],
                          sb + 16384 + off);
            }
#pragma unroll
            for (int h2 = 0; h2 < 2; h2++) {
                uint32_t bh[2][4], bl[2][4];
#pragma unroll
                for (int p2 = 0; p2 < 2; p2++) {
                    int ntb = h2 * 2 + p2;
                    int nrow = wn * 64 + ntb * 16 + (li >> 1) * 8 + lr;
                    int cb = kk * 2 + (li & 1);
                    uint32_t off = sw128((uint32_t)(nrow * 128 + cb * 16));
                    ldsm4(bh[p2][0], bh[p2][1], bh[p2][2], bh[p2][3],
                          sb + 32768 + off);
                    if (isQK)
                        ldsm4(bl[p2][0], bl[p2][1], bl[p2][2], bl[p2][3],
                              sb + 49152 + off);
                }
#pragma unroll
                for (int mt = 0; mt < 2; mt++)
#pragma unroll
                    for (int q = 0; q < 4; q++) {
                        int nt = h2 * 4 + q;
                        int p2 = q >> 1, od = q & 1;
                        float* c = acc[mt][nt];
                        mma16816(c, ah[mt], bh[p2][2 * od], bh[p2][2 * od + 1]);
                        if (isQK) {
                            mma16816(c, ah[mt], bl[p2][2 * od], bl[p2][2 * od + 1]);
                            mma16816(c, al[mt], bh[p2][2 * od], bh[p2][2 * od + 1]);
                        }
                    }
            }
        }
    }

    // ---- epilogue ----
    const int row0 = m0 + wm * 32 + gid;
#pragma unroll
    for (int mt = 0; mt < 2; mt++) {
        int rg = row0 + mt * 16;
        int b = rg >> 11, sI = rg & 2047;
#pragma unroll
        for (int nt = 0; nt < 8; nt++) {
            int ng = n0 + wn * 64 + nt * 8 + 2 * tig;
            int z = ng >> 9, r9 = ng & 511;
            int h = r9 >> 6, d = r9 & 63;
            size_t base = (((size_t)(b * HH + h)) * SS + sI) * DD + d;
            if (z == 2) {
                *(uint32_t*)(g_Vh + base) =
                    packh2(acc[mt][nt][0], acc[mt][nt][1]);
                *(uint32_t*)(g_Vh + base + 8 * DD) =
                    packh2(acc[mt][nt][2], acc[mt][nt][3]);
            } else {
                __half* oh = (z == 0) ? g_Qh : g_Kh;
                __half* ol = (z == 0) ? g_Ql : g_Kl;
                uint32_t hi, lo;
                split2h(acc[mt][nt][0], acc[mt][nt][1], hi, lo);
                *(uint32_t*)(oh + base) = hi;
                *(uint32_t*)(ol + base) = lo;
                split2h(acc[mt][nt][2], acc[mt][nt][3], hi, lo);
                *(uint32_t*)(oh + base + 8 * DD) = hi;
                *(uint32_t*)(ol + base + 8 * DD) = lo;
            }
        }
    }
}

// ---------------------------------------------------------------------------
// Proj GEMM, split-K, 1-pass (Av fp16 x Wp-hi): grid (32, 4, 2). Each CTA
// computes a 128x128 tile over half the K range (4 stages of k=64), writing
// its partial to g_p0 (kz=0) or g_p1 (kz=1) with plain stores. LN combines.
// Stage: Ah 16K + Bh 16K = 32KB; 3 stages = 96KB.
// ---------------------------------------------------------------------------
#define PJS_STAGE 32768
#define PJS_SMEM (3 * PJS_STAGE)    // 98304

__global__ __launch_bounds__(256, 1)
void proj_splitk_kernel() {
    extern __shared__ char sm[];
    const uint32_t smb = smem_u32(sm);
    const int t = threadIdx.x;
    const int w = t >> 5, l = t & 31;
    const int wm = w & 3, wn = w >> 2;
    const int gid = l >> 2, tig = l & 3;
    const int m0 = blockIdx.x * 128;
    const int n0 = blockIdx.y * 128;
    const int kbase = blockIdx.z * 256;
    float* outp = blockIdx.z ? g_p1 : g_p0;

    float acc[2][8][4];
#pragma unroll
    for (int i = 0; i < 2; i++)
#pragma unroll
        for (int j = 0; j < 8; j++)
#pragma unroll
            for (int c = 0; c < 4; c++) acc[i][j][c] = 0.f;

    auto issue_stage = [&](int s) {
        const int k0 = kbase + s * 64;
        const uint32_t sb = smb + (s % 3) * PJS_STAGE;
#pragma unroll
        for (int i = 0; i < 4; i++) {
            int c = t + 256 * i;
            int row = c >> 3, cb = c & 7;
            uint32_t swo = sw128((uint32_t)(row * 128 + cb * 16));
            cpasync16(sb + swo, g_Av + (size_t)(m0 + row) * EE + k0 + cb * 8);
            cpasync16(sb + 16384 + swo,
                      g_Bp_hi + (size_t)(n0 + row) * EE + k0 + cb * 8);
        }
        commitg();
    };

    issue_stage(0);
    issue_stage(1);

    const int li = l >> 3;
    const int lr = l & 7;

    for (int s = 0; s < 4; s++) {
        if (s < 3) waitg<1>(); else waitg<0>();
        __syncthreads();
        if (s + 2 < 4) issue_stage(s + 2);

        const uint32_t sb = smb + (s % 3) * PJS_STAGE;

#pragma unroll
        for (int kk = 0; kk < 4; kk++) {
            uint32_t ah[2][4];
#pragma unroll
            for (int mt = 0; mt < 2; mt++) {
                int row = wm * 32 + mt * 16 + (li & 1) * 8 + lr;
                int cb = kk * 2 + (li >> 1);
                uint32_t off = sw128((uint32_t)(row * 128 + cb * 16));
                ldsm4(ah[mt][0], ah[mt][1], ah[mt][2], ah[mt][3], sb + off);
            }
#pragma unroll
            for (int h2 = 0; h2 < 2; h2++) {
                uint32_t bh[2][4];
#pragma unroll
                for (int p2 = 0; p2 < 2; p2++) {
                    int ntb = h2 * 2 + p2;
                    int nrow = wn * 64 + ntb * 16 + (li >> 1) * 8 + lr;
                    int cb = kk * 2 + (li & 1);
                    uint32_t off = sw128((uint32_t)(nrow * 128 + cb * 16));
                    ldsm4(bh[p2][0], bh[p2][1], bh[p2][2], bh[p2][3],
                          sb + 16384 + off);
                }
#pragma unroll
                for (int mt = 0; mt < 2; mt++)
#pragma unroll
                    for (int q = 0; q < 4; q++) {
                        int nt = h2 * 4 + q;
                        int p2 = q >> 1, od = q & 1;
                        mma16816(acc[mt][nt], ah[mt],
                                 bh[p2][2 * od], bh[p2][2 * od + 1]);
                    }
            }
        }
    }

    // ---- epilogue: plain stores to partial buffer ----
    const int row0 = m0 + wm * 32 + gid;
#pragma unroll
    for (int mt = 0; mt < 2; mt++) {
        int rg = row0 + mt * 16;
#pragma unroll
        for (int nt = 0; nt < 8; nt++) {
            int ng = n0 + wn * 64 + nt * 8 + 2 * tig;
            *(float2*)(outp + (size_t)rg * EE + ng) =
                make_float2(acc[mt][nt][0], acc[mt][nt][1]);
            *(float2*)(outp + (size_t)(rg + 8) * EE + ng) =
                make_float2(acc[mt][nt][2], acc[mt][nt][3]);
        }
    }
}

// ---------------------------------------------------------------------------
// Flash attention: fp16 mma, fp32 accum. QK^T 3-pass (Q,K hi/lo);
// PV 1-pass. q-tile 128 rows, k-tiles of 64, 8 warps, 3-stage pipeline,
// warp-level masked-strip skip.
// ---------------------------------------------------------------------------
#define NEG_BIG (-1e30f)
#define SM_QH 0
#define SM_QL 16384
#define SM_STG 32768
#define STG_SZ 24576          // Kh 8K + Kl 8K + V 8K
#define OFF_KH 0
#define OFF_KL 8192
#define OFF_V 16384
#define ATTN_SMEM (SM_STG + 3 * STG_SZ)   // 106496

__global__ __launch_bounds__(256, 1)
void attn_mma_kernel() {
    extern __shared__ char sm[];
    const uint32_t smb = smem_u32(sm);
    const int t = threadIdx.x;
    const int w = t >> 5, l = t & 31;
    const int gid = l >> 2, tig = l & 3;
    const int li = l >> 3, lr = l & 7;

    const int bid = blockIdx.x;
    const int bh = bid & 15;
    const int qt = 15 - (bid >> 4);       // heavy tiles first
    const int b = bh >> 3, h = bh & 7;
    const int qs = qt * 128;
    const size_t bhoff = (size_t)bh * SS * DD;
    const int ktmax = 2 * qt + 1;

    // ---- issue Q (128x64 hi+lo); joins commit group of stage 0 ----
#pragma unroll
    for (int arr = 0; arr < 2; arr++) {
        const __half* g = arr ? g_Ql : g_Qh;
        uint32_t base = smb + (arr ? SM_QL : SM_QH);
#pragma unroll
        for (int i = 0; i < 4; i++) {
            int c = t + 256 * i;
            int row = c >> 3, cb = c & 7;
            cpasync16(base + sw128((uint32_t)(row * 128 + cb * 16)),
                      g + bhoff + (size_t)(qs + row) * DD + cb * 8);
        }
    }

    auto issue_stage = [&](int kt) {
        const uint32_t sb = smb + SM_STG + (kt % 3) * STG_SZ;
        const __half* gs[3] = {g_Kh, g_Kl, g_Vh};
        const int ks = kt * 64;
#pragma unroll
        for (int arr = 0; arr < 3; arr++) {
#pragma unroll
            for (int i = 0; i < 2; i++) {
                int c = t + 256 * i;
                int row = c >> 3, cb = c & 7;
                cpasync16(sb + arr * 8192 + sw128((uint32_t)(row * 128 + cb * 16)),
                          gs[arr] + bhoff + (size_t)(ks + row) * DD + cb * 8);
            }
        }
        commitg();
    };

    issue_stage(0);
    issue_stage(1);

    float O[8][4];
#pragma unroll
    for (int i = 0; i < 8; i++)
#pragma unroll
        for (int j = 0; j < 4; j++) O[i][j] = 0.f;
    float m0 = NEG_BIG, m1 = NEG_BIG, l0 = 0.f, l1 = 0.f;

    const int rowstrip = qs + w * 16;
    const int qg0 = rowstrip + gid;
    const int qg1 = qg0 + 8;

    for (int kt = 0; kt <= ktmax; kt++) {
        if (kt < ktmax) waitg<1>(); else waitg<0>();
        __syncthreads();
        if (kt + 2 <= ktmax) issue_stage(kt + 2);

        const uint32_t sb = smb + SM_STG + (kt % 3) * STG_SZ;
        const int ks = kt * 64;

        // warp-uniform skip: this warp's 16-row strip fully masked
        if (ks > rowstrip + 15) continue;

        // ---- S = Q K^T (3-pass fp16 hi/lo, fp32 acc) ----
        float S[8][4];
#pragma unroll
        for (int i = 0; i < 8; i++)
#pragma unroll
            for (int j = 0; j < 4; j++) S[i][j] = 0.f;

#pragma unroll
        for (int kk = 0; kk < 4; kk++) {
            uint32_t qh[4], ql[4];
            {
                int row = w * 16 + (li & 1) * 8 + lr;
                int cb = kk * 2 + (li >> 1);
                uint32_t off = sw128((uint32_t)(row * 128 + cb * 16));
                ldsm4(qh[0], qh[1], qh[2], qh[3], smb + SM_QH + off);
                ldsm4(ql[0], ql[1], ql[2], ql[3], smb + SM_QL + off);
            }
#pragma unroll
            for (int nb = 0; nb < 4; nb++) {
                uint32_t kh[4], kl[4];
                int nrow = nb * 16 + (li >> 1) * 8 + lr;
                int cb = kk * 2 + (li & 1);
                uint32_t off = sw128((uint32_t)(nrow * 128 + cb * 16));
                ldsm4(kh[0], kh[1], kh[2], kh[3], sb + OFF_KH + off);
                ldsm4(kl[0], kl[1], kl[2], kl[3], sb + OFF_KL + off);
#pragma unroll
                for (int od = 0; od < 2; od++) {
                    float* c = S[nb * 2 + od];
                    mma16816(c, qh, kh[2 * od], kh[2 * od + 1]);
                    mma16816(c, qh, kl[2 * od], kl[2 * od + 1]);
                    mma16816(c, ql, kh[2 * od], kh[2 * od + 1]);
                }
            }
        }

        // ---- causal mask ----
        if (ks + 63 > rowstrip) {
#pragma unroll
            for (int nt = 0; nt < 8; nt++) {
                int c0 = ks + nt * 8 + 2 * tig;
                if (c0 > qg0) S[nt][0] = NEG_BIG;
                if (c0 + 1 > qg0) S[nt][1] = NEG_BIG;
                if (c0 > qg1) S[nt][2] = NEG_BIG;
                if (c0 + 1 > qg1) S[nt][3] = NEG_BIG;
            }
        }

        // ---- online softmax ----
        float mx0 = NEG_BIG, mx1 = NEG_BIG;
#pragma unroll
        for (int nt = 0; nt < 8; nt++) {
            mx0 = fmaxf(mx0, fmaxf(S[nt][0], S[nt][1]));
            mx1 = fmaxf(mx1, fmaxf(S[nt][2], S[nt][3]));
        }
        mx0 = fmaxf(mx0, __shfl_xor_sync(0xffffffffu, mx0, 1));
        mx0 = fmaxf(mx0, __shfl_xor_sync(0xffffffffu, mx0, 2));
        mx1 = fmaxf(mx1, __shfl_xor_sync(0xffffffffu, mx1, 1));
        mx1 = fmaxf(mx1, __shfl_xor_sync(0xffffffffu, mx1, 2));

        float mn0 = fmaxf(m0, mx0), mn1 = fmaxf(m1, mx1);
        float sc0 = __expf(m0 - mn0), sc1 = __expf(m1 - mn1);
        float rs0 = 0.f, rs1 = 0.f;
#pragma unroll
        for (int nt = 0; nt < 8; nt++) {
            S[nt][0] = __expf(S[nt][0] - mn0);
            S[nt][1] = __expf(S[nt][1] - mn0);
            S[nt][2] = __expf(S[nt][2] - mn1);
            S[nt][3] = __expf(S[nt][3] - mn1);
            rs0 += S[nt][0] + S[nt][1];
            rs1 += S[nt][2] + S[nt][3];
        }
        rs0 += __shfl_xor_sync(0xffffffffu, rs0, 1);
        rs0 += __shfl_xor_sync(0xffffffffu, rs0, 2);
        rs1 += __shfl_xor_sync(0xffffffffu, rs1, 1);
        rs1 += __shfl_xor_sync(0xffffffffu, rs1, 2);
        l0 = l0 * sc0 + rs0;
        l1 = l1 * sc1 + rs1;
        m0 = mn0; m1 = mn1;
#pragma unroll
        for (int dt = 0; dt < 8; dt++) {
            O[dt][0] *= sc0; O[dt][1] *= sc0;
            O[dt][2] *= sc1; O[dt][3] *= sc1;
        }

        // ---- O += P V (1-pass: P fp16 x V fp16, fp32 acc) ----
#pragma unroll
        for (int kc = 0; kc < 4; kc++) {
            uint32_t pa[4];
            pa[0] = packh2(S[2 * kc][0],     S[2 * kc][1]);
            pa[1] = packh2(S[2 * kc][2],     S[2 * kc][3]);
            pa[2] = packh2(S[2 * kc + 1][0], S[2 * kc + 1][1]);
            pa[3] = packh2(S[2 * kc + 1][2], S[2 * kc + 1][3]);
#pragma unroll
            for (int db = 0; db < 4; db++) {
                uint32_t vh[4];
                int trow = kc * 16 + (li & 1) * 8 + lr;
                int dcb = (db * 16 + (li >> 1) * 8) * 2;
                uint32_t off = sw128((uint32_t)(trow * 128 + dcb));
                ldsm4t(vh[0], vh[1], vh[2], vh[3], sb + OFF_V + off);
#pragma unroll
                for (int od = 0; od < 2; od++)
                    mma16816(O[db * 2 + od], pa, vh[2 * od], vh[2 * od + 1]);
            }
        }
    }

    // ---- epilogue: vals[b, s, (7-h)*64+d] as single fp16 ----
    const float inv0 = 1.f / l0, inv1 = 1.f / l1;
    const int colbase = (HH - 1 - h) * DD;
#pragma unroll
    for (int dt = 0; dt < 8; dt++) {
        int d = dt * 8 + 2 * tig;
        size_t i0 = ((size_t)(b * SS + qg0)) * EE + colbase + d;
        size_t i1 = ((size_t)(b * SS + qg1)) * EE + colbase + d;
        *(uint32_t*)(g_Av + i0) = packh2(O[dt][0] * inv0, O[dt][1] * inv0);
        *(uint32_t*)(g_Av + i1) = packh2(O[dt][2] * inv1, O[dt][3] * inv1);
    }
}

// ---------------------------------------------------------------------------
// LayerNorm, fused combine: a = p0 + p1 + x + bp. 2 rows per 256-thread
// block, float4 per thread.
// ---------------------------------------------------------------------------
__global__ void ln_kernel(const float* __restrict__ x,
                          const float* __restrict__ bp,
                          const float* __restrict__ gamma,
                          const float* __restrict__ beta,
                          float* __restrict__ out) {
    const int t = threadIdx.x;
    const int rsub = t >> 7;
    const int tr = t & 127;
    const int row = blockIdx.x * 2 + rsub;
    const int e0 = tr * 4;
    const size_t base = (size_t)row * EE + e0;

    float4 p0 = *(const float4*)(g_p0 + base);
    float4 p1 = *(const float4*)(g_p1 + base);
    float4 xv = *(const float4*)(x + base);
    float4 bpv = *(const float4*)(bp + e0);
    float4 a;
    a.x = p0.x + p1.x + xv.x + bpv.x;
    a.y = p0.y + p1.y + xv.y + bpv.y;
    a.z = p0.z + p1.z + xv.z + bpv.z;
    a.w = p0.w + p1.w + xv.w + bpv.w;

    float s = a.x + a.y + a.z + a.w;
    float q = a.x * a.x + a.y * a.y + a.z * a.z + a.w * a.w;

#pragma unroll
    for (int off = 16; off; off >>= 1) {
        s += __shfl_xor_sync(0xffffffffu, s, off);
        q += __shfl_xor_sync(0xffffffffu, q, off);
    }
    __shared__ float ss[2][4], sq[2][4];
    int wir = (t >> 5) & 3;
    if ((t & 31) == 0) { ss[rsub][wir] = s; sq[rsub][wir] = q; }
    __syncthreads();

    float S = ss[rsub][0] + ss[rsub][1] + ss[rsub][2] + ss[rsub][3];
    float Q2 = sq[rsub][0] + sq[rsub][1] + sq[rsub][2] + sq[rsub][3];

    float mu  = S * (1.f / EE);
    float var = Q2 * (1.f / EE) - mu * mu;
    float inv = rsqrtf(var + 1e-5f);

    float4 g = *(const float4*)(gamma + e0);
    float4 be = *(const float4*)(beta + e0);
    float4 o;
    o.x = (a.x - mu) * inv * g.x + be.x;
    o.y = (a.y - mu) * inv * g.y + be.y;
    o.z = (a.z - mu) * inv * g.z + be.z;
    o.w = (a.w - mu) * inv * g.w + be.w;
    *(float4*)(out + base) = o;
}

// ---------------------------------------------------------------------------
extern "C" void kernel_launch(void* const* d_in, const int* in_sizes, int n_in,
                              void* d_out, int out_size) {
    const float* x     = (const float*)d_in[0];
    const float* Wq    = (const float*)d_in[1];
    const float* Wk    = (const float*)d_in[2];
    const float* Wv    = (const float*)d_in[3];
    const float* Wp    = (const float*)d_in[4];
    const float* bp    = (const float*)d_in[5];
    const float* gamma = (const float*)d_in[6];
    const float* beta  = (const float*)d_in[7];
    float* out = (float*)d_out;

    cudaFuncSetAttribute(gemm_mma_kernel, cudaFuncAttributeMaxDynamicSharedMemorySize, GEMM_SMEM);
    cudaFuncSetAttribute(proj_splitk_kernel, cudaFuncAttributeMaxDynamicSharedMemorySize, PJS_SMEM);
    cudaFuncSetAttribute(attn_mma_kernel, cudaFuncAttributeMaxDynamicSharedMemorySize, ATTN_SMEM);

    prep_all_kernel<<<PREP_BLOCKS, 256>>>(Wq, Wk, Wv, Wp, x);

    gemm_mma_kernel<<<dim3(MM / 128, 12), 256, GEMM_SMEM>>>(x);
    attn_mma_kernel<<<256, 256, ATTN_SMEM>>>();
    proj_splitk_kernel<<<dim3(MM / 128, 4, 2), 256, PJS_SMEM>>>();
    ln_kernel<<<MM / 2, 256>>>(x, bp, gamma, beta, out);
}